// round 2
// baseline (speedup 1.0000x reference)
#include <cuda_runtime.h>

// ---------------- problem constants ----------------
// B=8, C1=512, C=256, D=256, NH=8, NP=4, NL=1, H=W=64, L=4096
#define HWP 4096   // H*W
#define NB  8

// ---------------- scratch buffers (device globals; no allocation) ----------------
__device__ float g_y0 [8L*512*4096];  // cv1 output  [B,512,HW]  (a = ch 0-255, b = ch 256-511)
__device__ float g_t  [8L*256*4096];  // conv temp   [B,256,HW]
__device__ float g_b1 [8L*256*4096];
__device__ float g_b2 [8L*256*4096];
__device__ float g_val[8L*4096*256];  // value       [B,L,D]
__device__ float g_off[8L*4096*64];   // offsets     [B,L,64]
__device__ float g_aw [8L*4096*32];   // attn logits [B,L,32]
__device__ float g_smp[8L*4096*256];  // sampled     [B,L,D]
__device__ float g_at [8L*256*4096];  // attn out    [B,D,L]  (transposed for concat)

static __device__ __forceinline__ float silu_f(float x) {
    return x / (1.0f + __expf(-x));
}

#define BM 128
#define BN 128
#define BKK 8

// ---------------- generic fp32 GEMM: C[m,n] = act(sum_k a(m,k)*b(k,n) + bias) ----------------
// TA: a(m,k) = A[k*M+m] else A[m*K+k]
// TB: b(k,n) = B[n*K+k] else B[k*N+n]
// ACT: 0 none, 1 silu.  BIAS: 0 none, 1 bias[n], 2 bias[m]
template<bool TA, bool TB, int ACT, int BIAS>
__global__ __launch_bounds__(256, 2)
void gemm_k(const float* __restrict__ A, const float* __restrict__ Bm,
            const float* __restrict__ bias, float* __restrict__ Cm,
            int M, int N, int K, long sA, long sB, long sC)
{
    const int bz = blockIdx.z;
    A  += (long)bz * sA;
    Bm += (long)bz * sB;
    Cm += (long)bz * sC;
    const int n0 = blockIdx.x * BN;
    const int m0 = blockIdx.y * BM;
    __shared__ float As[BKK][BM];
    __shared__ float Bs[BKK][BN];
    const int tid = threadIdx.x;
    const int tx = tid & 15, ty = tid >> 4;
    float acc[8][8];
#pragma unroll
    for (int i = 0; i < 8; i++)
#pragma unroll
        for (int j = 0; j < 8; j++) acc[i][j] = 0.f;

    for (int k0 = 0; k0 < K; k0 += BKK) {
        if (TA) {
            const int i = (tid & 31) * 4, kk = tid >> 5;
            float4 v = *(const float4*)(A + (long)(k0 + kk) * M + m0 + i);
            *(float4*)&As[kk][i] = v;
        } else {
            const int mi = tid >> 1, kk4 = (tid & 1) * 4;
            float4 v = *(const float4*)(A + (long)(m0 + mi) * K + k0 + kk4);
            As[kk4 + 0][mi] = v.x; As[kk4 + 1][mi] = v.y;
            As[kk4 + 2][mi] = v.z; As[kk4 + 3][mi] = v.w;
        }
        if (TB) {
            const int ni = tid >> 1, kk4 = (tid & 1) * 4;
            float4 v = make_float4(0.f, 0.f, 0.f, 0.f);
            if (n0 + ni < N) v = *(const float4*)(Bm + (long)(n0 + ni) * K + k0 + kk4);
            Bs[kk4 + 0][ni] = v.x; Bs[kk4 + 1][ni] = v.y;
            Bs[kk4 + 2][ni] = v.z; Bs[kk4 + 3][ni] = v.w;
        } else {
            const int j = (tid & 31) * 4, kk = tid >> 5;
            float4 v = make_float4(0.f, 0.f, 0.f, 0.f);
            if (n0 + j < N) v = *(const float4*)(Bm + (long)(k0 + kk) * N + n0 + j);
            *(float4*)&Bs[kk][j] = v;
        }
        __syncthreads();
#pragma unroll
        for (int kk = 0; kk < BKK; kk++) {
            float a[8], b[8];
            *(float4*)(a)     = *(float4*)&As[kk][ty * 8];
            *(float4*)(a + 4) = *(float4*)&As[kk][ty * 8 + 4];
            *(float4*)(b)     = *(float4*)&Bs[kk][tx * 8];
            *(float4*)(b + 4) = *(float4*)&Bs[kk][tx * 8 + 4];
#pragma unroll
            for (int i = 0; i < 8; i++)
#pragma unroll
                for (int j = 0; j < 8; j++) acc[i][j] += a[i] * b[j];
        }
        __syncthreads();
    }
#pragma unroll
    for (int i = 0; i < 8; i++) {
        const int m = m0 + ty * 8 + i;
        const float bmv = (BIAS == 2) ? bias[m] : 0.f;
#pragma unroll
        for (int jj = 0; jj < 2; jj++) {
            const int n = n0 + tx * 8 + jj * 4;
            if (n < N) {
                float4 v;
                v.x = acc[i][jj * 4 + 0]; v.y = acc[i][jj * 4 + 1];
                v.z = acc[i][jj * 4 + 2]; v.w = acc[i][jj * 4 + 3];
                if (BIAS == 1) {
                    v.x += bias[n]; v.y += bias[n + 1]; v.z += bias[n + 2]; v.w += bias[n + 3];
                } else if (BIAS == 2) {
                    v.x += bmv; v.y += bmv; v.z += bmv; v.w += bmv;
                }
                if (ACT == 1) {
                    v.x = silu_f(v.x); v.y = silu_f(v.y);
                    v.z = silu_f(v.z); v.w = silu_f(v.w);
                }
                *(float4*)(Cm + (long)m * N + n) = v;
            }
        }
    }
}

// ---------------- 3x3 conv as implicit-im2col GEMM, fused SiLU ----------------
// Out[co, p] = silu( sum_{ci,ky,kx} W[co][ci][ky][kx] * In[ci][y+ky-1][x+kx-1] )
// M=256, N=4096, K=2304
__global__ __launch_bounds__(256, 2)
void conv3_k(const float* __restrict__ In, const float* __restrict__ Wt,
             float* __restrict__ Out, long sIn, long sOut)
{
    const int K = 2304, N = 4096;
    const int bz = blockIdx.z;
    In  += (long)bz * sIn;
    Out += (long)bz * sOut;
    const int n0 = blockIdx.x * BN;
    const int m0 = blockIdx.y * BM;
    __shared__ float As[BKK][BM];
    __shared__ float Bs[BKK][BN];
    const int tid = threadIdx.x;
    const int tx = tid & 15, ty = tid >> 4;
    float acc[8][8];
#pragma unroll
    for (int i = 0; i < 8; i++)
#pragma unroll
        for (int j = 0; j < 8; j++) acc[i][j] = 0.f;

    for (int k0 = 0; k0 < K; k0 += BKK) {
        {   // A: weights [256][2304]
            const int mi = tid >> 1, kk4 = (tid & 1) * 4;
            float4 v = *(const float4*)(Wt + (long)(m0 + mi) * K + k0 + kk4);
            As[kk4 + 0][mi] = v.x; As[kk4 + 1][mi] = v.y;
            As[kk4 + 2][mi] = v.z; As[kk4 + 3][mi] = v.w;
        }
        {   // B: implicit im2col with zero padding
            const int kk = tid >> 5;
            const int j0 = (tid & 31) * 4;
            const int kidx = k0 + kk;
            const int ci = kidx / 9;
            const int r  = kidx - ci * 9;
            const int ky = r / 3 - 1;
            const int kx = (r - (r / 3) * 3) - 1;
            const float* inC = In + (long)ci * 4096;
#pragma unroll
            for (int jj = 0; jj < 4; jj++) {
                const int n = n0 + j0 + jj;
                const int y = (n >> 6) + ky;
                const int x = (n & 63) + kx;
                float v = 0.f;
                if ((unsigned)y < 64u && (unsigned)x < 64u) v = inC[(y << 6) + x];
                Bs[kk][j0 + jj] = v;
            }
        }
        __syncthreads();
#pragma unroll
        for (int kk = 0; kk < BKK; kk++) {
            float a[8], b[8];
            *(float4*)(a)     = *(float4*)&As[kk][ty * 8];
            *(float4*)(a + 4) = *(float4*)&As[kk][ty * 8 + 4];
            *(float4*)(b)     = *(float4*)&Bs[kk][tx * 8];
            *(float4*)(b + 4) = *(float4*)&Bs[kk][tx * 8 + 4];
#pragma unroll
            for (int i = 0; i < 8; i++)
#pragma unroll
                for (int j = 0; j < 8; j++) acc[i][j] += a[i] * b[j];
        }
        __syncthreads();
    }
#pragma unroll
    for (int i = 0; i < 8; i++) {
        const int m = m0 + ty * 8 + i;
#pragma unroll
        for (int jj = 0; jj < 2; jj++) {
            const int n = n0 + tx * 8 + jj * 4;
            float4 v;
            v.x = silu_f(acc[i][jj * 4 + 0]); v.y = silu_f(acc[i][jj * 4 + 1]);
            v.z = silu_f(acc[i][jj * 4 + 2]); v.w = silu_f(acc[i][jj * 4 + 3]);
            *(float4*)(Out + (long)m * N + n) = v;
        }
    }
}

// ---------------- cv2: 1x1 conv over virtual concat [a,b,b1,b2,attn], fused SiLU ----------------
// M=512, N=4096, K=1280
__global__ __launch_bounds__(256, 2)
void cv2_k(const float* __restrict__ Wt, float* __restrict__ Out)
{
    const int K = 1280, N = 4096;
    const int bz = blockIdx.z;
    Out += (long)bz * (512L * 4096);
    const int n0 = blockIdx.x * BN;
    const int m0 = blockIdx.y * BM;
    __shared__ float As[BKK][BM];
    __shared__ float Bs[BKK][BN];
    const int tid = threadIdx.x;
    const int tx = tid & 15, ty = tid >> 4;
    float acc[8][8];
#pragma unroll
    for (int i = 0; i < 8; i++)
#pragma unroll
        for (int j = 0; j < 8; j++) acc[i][j] = 0.f;

    for (int k0 = 0; k0 < K; k0 += BKK) {
        {   // A: weights [512][1280]
            const int mi = tid >> 1, kk4 = (tid & 1) * 4;
            float4 v = *(const float4*)(Wt + (long)(m0 + mi) * K + k0 + kk4);
            As[kk4 + 0][mi] = v.x; As[kk4 + 1][mi] = v.y;
            As[kk4 + 2][mi] = v.z; As[kk4 + 3][mi] = v.w;
        }
        {   // B: virtual concat gather
            const int kk = tid >> 5;
            const int j  = (tid & 31) * 4;
            const int ci = k0 + kk;
            const float* src;
            if (ci < 512)       src = g_y0 + (long)bz * (512L * 4096) + (long)ci * 4096;
            else if (ci < 768)  src = g_b1 + (long)bz * (256L * 4096) + (long)(ci - 512) * 4096;
            else if (ci < 1024) src = g_b2 + (long)bz * (256L * 4096) + (long)(ci - 768) * 4096;
            else                src = g_at + (long)bz * (256L * 4096) + (long)(ci - 1024) * 4096;
            *(float4*)&Bs[kk][j] = *(const float4*)(src + n0 + j);
        }
        __syncthreads();
#pragma unroll
        for (int kk = 0; kk < BKK; kk++) {
            float a[8], b[8];
            *(float4*)(a)     = *(float4*)&As[kk][ty * 8];
            *(float4*)(a + 4) = *(float4*)&As[kk][ty * 8 + 4];
            *(float4*)(b)     = *(float4*)&Bs[kk][tx * 8];
            *(float4*)(b + 4) = *(float4*)&Bs[kk][tx * 8 + 4];
#pragma unroll
            for (int i = 0; i < 8; i++)
#pragma unroll
                for (int j = 0; j < 8; j++) acc[i][j] += a[i] * b[j];
        }
        __syncthreads();
    }
#pragma unroll
    for (int i = 0; i < 8; i++) {
        const int m = m0 + ty * 8 + i;
#pragma unroll
        for (int jj = 0; jj < 2; jj++) {
            const int n = n0 + tx * 8 + jj * 4;
            float4 v;
            v.x = silu_f(acc[i][jj * 4 + 0]); v.y = silu_f(acc[i][jj * 4 + 1]);
            v.z = silu_f(acc[i][jj * 4 + 2]); v.w = silu_f(acc[i][jj * 4 + 3]);
            *(float4*)(Out + (long)m * N + n) = v;
        }
    }
}

// ---------------- deformable sampling: softmax(4) + bilinear gather + weighted sum ----------------
// one warp per (l, head); lane = dh channel. grid = (L, B), block = 256 (8 warps = 8 heads)
__global__ __launch_bounds__(256)
void sample_k(const float* __restrict__ bbox)
{
    const int l = blockIdx.x, b = blockIdx.y;
    const int h = threadIdx.x >> 5, lane = threadIdx.x & 31;
    const long bl = (long)b * 4096 + l;
    const float* offp = g_off + bl * 64 + h * 8;
    const float* awp  = g_aw  + bl * 32 + h * 4;
    const float bx = bbox[bl * 2 + 0] * 64.f - 0.5f;
    const float by = bbox[bl * 2 + 1] * 64.f - 0.5f;

    const float a0 = awp[0], a1 = awp[1], a2 = awp[2], a3 = awp[3];
    const float mx = fmaxf(fmaxf(a0, a1), fmaxf(a2, a3));
    const float e0 = __expf(a0 - mx), e1 = __expf(a1 - mx);
    const float e2 = __expf(a2 - mx), e3 = __expf(a3 - mx);
    const float inv = 1.f / (e0 + e1 + e2 + e3);
    float ew[4] = { e0 * inv, e1 * inv, e2 * inv, e3 * inv };

    const float* valb = g_val + (long)b * (4096L * 256) + h * 32 + lane;
    float acc = 0.f;
#pragma unroll
    for (int p = 0; p < 4; p++) {
        const float gx = bx + offp[p * 2 + 0];
        const float gy = by + offp[p * 2 + 1];
        const float fx = floorf(gx), fy = floorf(gy);
        const int x0 = (int)fx, y0 = (int)fy;
        const float wx1 = gx - fx, wy1 = gy - fy;
        const float wx0 = 1.f - wx1, wy0 = 1.f - wy1;
        const bool vx0 = (unsigned)x0 < 64u, vx1 = (unsigned)(x0 + 1) < 64u;
        const bool vy0 = (unsigned)y0 < 64u, vy1 = (unsigned)(y0 + 1) < 64u;
        float v = 0.f;
        if (vy0) {
            const float* row = valb + ((long)y0 << 6) * 256;
            if (vx0) v += wx0 * wy0 * row[(long)x0 * 256];
            if (vx1) v += wx1 * wy0 * row[(long)(x0 + 1) * 256];
        }
        if (vy1) {
            const float* row = valb + ((long)(y0 + 1) << 6) * 256;
            if (vx0) v += wx0 * wy1 * row[(long)x0 * 256];
            if (vx1) v += wx1 * wy1 * row[(long)(x0 + 1) * 256];
        }
        acc += ew[p] * v;
    }
    g_smp[bl * 256 + h * 32 + lane] = acc;
}

// ---------------- launch ----------------
extern "C" void kernel_launch(void* const* d_in, const int* in_sizes, int n_in,
                              void* d_out, int out_size)
{
    const float* x       = (const float*)d_in[0];
    const float* bbox    = (const float*)d_in[1];
    // d_in[2] = value_shapes (constants [64,64]) — unused
    const float* cv1_w   = (const float*)d_in[3];
    const float* m0c1    = (const float*)d_in[4];
    const float* m0c2    = (const float*)d_in[5];
    const float* m1c1    = (const float*)d_in[6];
    const float* m1c2    = (const float*)d_in[7];
    const float* vproj_w = (const float*)d_in[8];
    const float* vproj_b = (const float*)d_in[9];
    const float* off_w   = (const float*)d_in[10];
    const float* off_b   = (const float*)d_in[11];
    const float* aw_w    = (const float*)d_in[12];
    const float* aw_b    = (const float*)d_in[13];
    const float* out_w   = (const float*)d_in[14];
    const float* out_b   = (const float*)d_in[15];
    const float* cv2_w   = (const float*)d_in[16];
    float* out = (float*)d_out;

    float *p_y0, *p_t, *p_b1, *p_b2, *p_val, *p_off, *p_aw, *p_smp, *p_at;
    cudaGetSymbolAddress((void**)&p_y0,  g_y0);
    cudaGetSymbolAddress((void**)&p_t,   g_t);
    cudaGetSymbolAddress((void**)&p_b1,  g_b1);
    cudaGetSymbolAddress((void**)&p_b2,  g_b2);
    cudaGetSymbolAddress((void**)&p_val, g_val);
    cudaGetSymbolAddress((void**)&p_off, g_off);
    cudaGetSymbolAddress((void**)&p_aw,  g_aw);
    cudaGetSymbolAddress((void**)&p_smp, g_smp);
    cudaGetSymbolAddress((void**)&p_at,  g_at);

    dim3 blk(256);

    // cv1: y0 = silu(W[512,512] @ x[b])   C[co, p]
    gemm_k<false, false, 1, 0><<<dim3(32, 4, NB), blk>>>(
        cv1_w, x, nullptr, p_y0, 512, 4096, 512, 0L, 512L * 4096, 512L * 4096);

    // conv3 chain: b -> t -> b1 -> t -> b2
    conv3_k<<<dim3(32, 2, NB), blk>>>(p_y0 + 256L * 4096, m0c1, p_t,  512L * 4096, 256L * 4096);
    conv3_k<<<dim3(32, 2, NB), blk>>>(p_t,                m0c2, p_b1, 256L * 4096, 256L * 4096);
    conv3_k<<<dim3(32, 2, NB), blk>>>(p_b1,               m1c1, p_t,  256L * 4096, 256L * 4096);
    conv3_k<<<dim3(32, 2, NB), blk>>>(p_t,                m1c2, p_b2, 256L * 4096, 256L * 4096);

    // value = q @ vproj_w + b  (q[l,c] = b2[c,l] -> TA)   [B,L,256]
    gemm_k<true, false, 0, 1><<<dim3(2, 32, NB), blk>>>(
        p_b2, vproj_w, vproj_b, p_val, 4096, 256, 256, 256L * 4096, 0L, 4096L * 256);

    // off = q @ off_w + b   [B,L,64]
    gemm_k<true, false, 0, 1><<<dim3(1, 32, NB), blk>>>(
        p_b2, off_w, off_b, p_off, 4096, 64, 256, 256L * 4096, 0L, 4096L * 64);

    // aw logits = q @ aw_w + b   [B,L,32]
    gemm_k<true, false, 0, 1><<<dim3(1, 32, NB), blk>>>(
        p_b2, aw_w, aw_b, p_aw, 4096, 32, 256, 256L * 4096, 0L, 4096L * 32);

    // softmax + bilinear sampling -> g_smp [B,L,256]
    sample_k<<<dim3(4096, NB), blk>>>(bbox);

    // attn^T = out_w^T @ samp^T + out_b   ->  g_at [B,D,L]
    gemm_k<true, true, 0, 2><<<dim3(32, 2, NB), blk>>>(
        out_w, p_smp, out_b, p_at, 256, 4096, 256, 0L, 4096L * 256, 256L * 4096);

    // cv2 over virtual concat -> d_out [B,512,HW]
    cv2_k<<<dim3(32, 4, NB), blk>>>(cv2_w, out);
}

// round 6
// speedup vs baseline: 1.0886x; 1.0886x over previous
#include <cuda_runtime.h>

// ---------------- problem constants ----------------
// B=8, C1=512, C=256, D=256, NH=8, NP=4, NL=1, H=W=64, L=4096
#define HWP 4096   // H*W
#define NB  8

// ---------------- scratch buffers (device globals; no allocation) ----------------
__device__ float g_y0 [8L*512*4096];  // cv1 output  [B,512,HW]  (a = ch 0-255, b = ch 256-511)
__device__ float g_t  [8L*256*4096];  // conv temp   [B,256,HW]
__device__ float g_b1 [8L*256*4096];
__device__ float g_b2 [8L*256*4096];
__device__ float g_val[8L*4096*256];  // value       [B,L,D]
__device__ float g_off[8L*4096*64];   // offsets     [B,L,64]
__device__ float g_aw [8L*4096*32];   // attn logits [B,L,32]
__device__ float g_smp[8L*4096*256];  // sampled     [B,L,D]
__device__ float g_at [8L*256*4096];  // attn out    [B,D,L]  (transposed for concat)

static __device__ __forceinline__ float silu_f(float x) {
    return x / (1.0f + __expf(-x));
}

// ---------------- packed fp32x2 helpers (sm_100+ f32x2 pipe) ----------------
typedef unsigned long long u64;

static __device__ __forceinline__ u64 dup2(float x) {
    u64 r;
    asm("mov.b64 %0, {%1, %1};" : "=l"(r) : "r"(__float_as_uint(x)));
    return r;
}
static __device__ __forceinline__ void fma2(u64& d, u64 a, u64 b) {
    asm("fma.rn.f32x2 %0, %1, %2, %3;" : "=l"(d) : "l"(a), "l"(b), "l"(d));
}
static __device__ __forceinline__ float2 unpk2(u64 v) {
    float2 r;
    asm("mov.b64 {%0, %1}, %2;" : "=f"(r.x), "=f"(r.y) : "l"(v));
    return r;
}

#define BM 128
#define BN 128
#define BKK 8

// shared inner product: acc2[i][j] += (a_i, a_i) * (b_{2j}, b_{2j+1})
#define MICRO_MMA(As_, Bs_)                                                     \
    _Pragma("unroll")                                                           \
    for (int kk = 0; kk < BKK; kk++) {                                          \
        float a[8];                                                             \
        *(float4*)(a)     = *(float4*)&As_[kk][ty * 8];                         \
        *(float4*)(a + 4) = *(float4*)&As_[kk][ty * 8 + 4];                     \
        ulonglong2 t0 = *(const ulonglong2*)&Bs_[kk][tx * 8];                   \
        ulonglong2 t1 = *(const ulonglong2*)&Bs_[kk][tx * 8 + 4];               \
        u64 b2[4]; b2[0] = t0.x; b2[1] = t0.y; b2[2] = t1.x; b2[3] = t1.y;      \
        u64 a2[8];                                                              \
        _Pragma("unroll")                                                       \
        for (int i = 0; i < 8; i++) a2[i] = dup2(a[i]);                         \
        _Pragma("unroll")                                                       \
        for (int i = 0; i < 8; i++)                                             \
            _Pragma("unroll")                                                   \
            for (int j = 0; j < 4; j++) fma2(acc2[i][j], a2[i], b2[j]);         \
    }

// ---------------- generic fp32 GEMM: C[m,n] = act(sum_k a(m,k)*b(k,n) + bias) ----------------
// TA: a(m,k) = A[k*M+m] else A[m*K+k]
// TB: b(k,n) = B[n*K+k] else B[k*N+n]
// ACT: 0 none, 1 silu.  BIAS: 0 none, 1 bias[n], 2 bias[m]
template<bool TA, bool TB, int ACT, int BIAS>
__global__ __launch_bounds__(256, 2)
void gemm_k(const float* __restrict__ A, const float* __restrict__ Bm,
            const float* __restrict__ bias, float* __restrict__ Cm,
            int M, int N, int K, long sA, long sB, long sC)
{
    const int bz = blockIdx.z;
    A  += (long)bz * sA;
    Bm += (long)bz * sB;
    Cm += (long)bz * sC;
    const int n0 = blockIdx.x * BN;
    const int m0 = blockIdx.y * BM;
    __shared__ float As[BKK][BM];
    __shared__ float Bs[BKK][BN];
    const int tid = threadIdx.x;
    const int tx = tid & 15, ty = tid >> 4;
    u64 acc2[8][4];
#pragma unroll
    for (int i = 0; i < 8; i++)
#pragma unroll
        for (int j = 0; j < 4; j++) acc2[i][j] = 0ull;

    for (int k0 = 0; k0 < K; k0 += BKK) {
        if (TA) {
            const int i = (tid & 31) * 4, kk = tid >> 5;
            float4 v = *(const float4*)(A + (long)(k0 + kk) * M + m0 + i);
            *(float4*)&As[kk][i] = v;
        } else {
            const int mi = tid >> 1, kk4 = (tid & 1) * 4;
            float4 v = *(const float4*)(A + (long)(m0 + mi) * K + k0 + kk4);
            As[kk4 + 0][mi] = v.x; As[kk4 + 1][mi] = v.y;
            As[kk4 + 2][mi] = v.z; As[kk4 + 3][mi] = v.w;
        }
        if (TB) {
            const int ni = tid >> 1, kk4 = (tid & 1) * 4;
            float4 v = make_float4(0.f, 0.f, 0.f, 0.f);
            if (n0 + ni < N) v = *(const float4*)(Bm + (long)(n0 + ni) * K + k0 + kk4);
            Bs[kk4 + 0][ni] = v.x; Bs[kk4 + 1][ni] = v.y;
            Bs[kk4 + 2][ni] = v.z; Bs[kk4 + 3][ni] = v.w;
        } else {
            const int j = (tid & 31) * 4, kk = tid >> 5;
            float4 v = make_float4(0.f, 0.f, 0.f, 0.f);
            if (n0 + j < N) v = *(const float4*)(Bm + (long)(k0 + kk) * N + n0 + j);
            *(float4*)&Bs[kk][j] = v;
        }
        __syncthreads();
        MICRO_MMA(As, Bs)
        __syncthreads();
    }
#pragma unroll
    for (int i = 0; i < 8; i++) {
        const int m = m0 + ty * 8 + i;
        const float bmv = (BIAS == 2) ? bias[m] : 0.f;
        float av[8];
#pragma unroll
        for (int j = 0; j < 4; j++) {
            float2 p = unpk2(acc2[i][j]);
            av[2 * j] = p.x; av[2 * j + 1] = p.y;
        }
#pragma unroll
        for (int jj = 0; jj < 2; jj++) {
            const int n = n0 + tx * 8 + jj * 4;
            if (n < N) {
                float4 v;
                v.x = av[jj * 4 + 0]; v.y = av[jj * 4 + 1];
                v.z = av[jj * 4 + 2]; v.w = av[jj * 4 + 3];
                if (BIAS == 1) {
                    v.x += bias[n]; v.y += bias[n + 1]; v.z += bias[n + 2]; v.w += bias[n + 3];
                } else if (BIAS == 2) {
                    v.x += bmv; v.y += bmv; v.z += bmv; v.w += bmv;
                }
                if (ACT == 1) {
                    v.x = silu_f(v.x); v.y = silu_f(v.y);
                    v.z = silu_f(v.z); v.w = silu_f(v.w);
                }
                *(float4*)(Cm + (long)m * N + n) = v;
            }
        }
    }
}

// ---------------- 3x3 conv as implicit-im2col GEMM, fused SiLU ----------------
// M=256, N=4096, K=2304
__global__ __launch_bounds__(256, 2)
void conv3_k(const float* __restrict__ In, const float* __restrict__ Wt,
             float* __restrict__ Out, long sIn, long sOut)
{
    const int K = 2304, N = 4096;
    const int bz = blockIdx.z;
    In  += (long)bz * sIn;
    Out += (long)bz * sOut;
    const int n0 = blockIdx.x * BN;
    const int m0 = blockIdx.y * BM;
    __shared__ float As[BKK][BM];
    __shared__ float Bs[BKK][BN];
    const int tid = threadIdx.x;
    const int tx = tid & 15, ty = tid >> 4;
    u64 acc2[8][4];
#pragma unroll
    for (int i = 0; i < 8; i++)
#pragma unroll
        for (int j = 0; j < 4; j++) acc2[i][j] = 0ull;

    for (int k0 = 0; k0 < K; k0 += BKK) {
        {   // A: weights [256][2304]
            const int mi = tid >> 1, kk4 = (tid & 1) * 4;
            float4 v = *(const float4*)(Wt + (long)(m0 + mi) * K + k0 + kk4);
            As[kk4 + 0][mi] = v.x; As[kk4 + 1][mi] = v.y;
            As[kk4 + 2][mi] = v.z; As[kk4 + 3][mi] = v.w;
        }
        {   // B: implicit im2col with zero padding
            const int kk = tid >> 5;
            const int j0 = (tid & 31) * 4;
            const int kidx = k0 + kk;
            const int ci = kidx / 9;
            const int r  = kidx - ci * 9;
            const int ky = r / 3 - 1;
            const int kx = (r - (r / 3) * 3) - 1;
            const float* inC = In + (long)ci * 4096;
#pragma unroll
            for (int jj = 0; jj < 4; jj++) {
                const int n = n0 + j0 + jj;
                const int y = (n >> 6) + ky;
                const int x = (n & 63) + kx;
                float v = 0.f;
                if ((unsigned)y < 64u && (unsigned)x < 64u) v = inC[(y << 6) + x];
                Bs[kk][j0 + jj] = v;
            }
        }
        __syncthreads();
        MICRO_MMA(As, Bs)
        __syncthreads();
    }
#pragma unroll
    for (int i = 0; i < 8; i++) {
        const int m = m0 + ty * 8 + i;
        float av[8];
#pragma unroll
        for (int j = 0; j < 4; j++) {
            float2 p = unpk2(acc2[i][j]);
            av[2 * j] = p.x; av[2 * j + 1] = p.y;
        }
#pragma unroll
        for (int jj = 0; jj < 2; jj++) {
            const int n = n0 + tx * 8 + jj * 4;
            float4 v;
            v.x = silu_f(av[jj * 4 + 0]); v.y = silu_f(av[jj * 4 + 1]);
            v.z = silu_f(av[jj * 4 + 2]); v.w = silu_f(av[jj * 4 + 3]);
            *(float4*)(Out + (long)m * N + n) = v;
        }
    }
}

// ---------------- cv2: 1x1 conv over virtual concat [a,b,b1,b2,attn], fused SiLU ----------------
// M=512, N=4096, K=1280
__global__ __launch_bounds__(256, 2)
void cv2_k(const float* __restrict__ Wt, float* __restrict__ Out)
{
    const int K = 1280, N = 4096;
    const int bz = blockIdx.z;
    Out += (long)bz * (512L * 4096);
    const int n0 = blockIdx.x * BN;
    const int m0 = blockIdx.y * BM;
    __shared__ float As[BKK][BM];
    __shared__ float Bs[BKK][BN];
    const int tid = threadIdx.x;
    const int tx = tid & 15, ty = tid >> 4;
    u64 acc2[8][4];
#pragma unroll
    for (int i = 0; i < 8; i++)
#pragma unroll
        for (int j = 0; j < 4; j++) acc2[i][j] = 0ull;

    for (int k0 = 0; k0 < K; k0 += BKK) {
        {   // A: weights [512][1280]
            const int mi = tid >> 1, kk4 = (tid & 1) * 4;
            float4 v = *(const float4*)(Wt + (long)(m0 + mi) * K + k0 + kk4);
            As[kk4 + 0][mi] = v.x; As[kk4 + 1][mi] = v.y;
            As[kk4 + 2][mi] = v.z; As[kk4 + 3][mi] = v.w;
        }
        {   // B: virtual concat gather
            const int kk = tid >> 5;
            const int j  = (tid & 31) * 4;
            const int ci = k0 + kk;
            const float* src;
            if (ci < 512)       src = g_y0 + (long)bz * (512L * 4096) + (long)ci * 4096;
            else if (ci < 768)  src = g_b1 + (long)bz * (256L * 4096) + (long)(ci - 512) * 4096;
            else if (ci < 1024) src = g_b2 + (long)bz * (256L * 4096) + (long)(ci - 768) * 4096;
            else                src = g_at + (long)bz * (256L * 4096) + (long)(ci - 1024) * 4096;
            *(float4*)&Bs[kk][j] = *(const float4*)(src + n0 + j);
        }
        __syncthreads();
        MICRO_MMA(As, Bs)
        __syncthreads();
    }
#pragma unroll
    for (int i = 0; i < 8; i++) {
        const int m = m0 + ty * 8 + i;
        float av[8];
#pragma unroll
        for (int j = 0; j < 4; j++) {
            float2 p = unpk2(acc2[i][j]);
            av[2 * j] = p.x; av[2 * j + 1] = p.y;
        }
#pragma unroll
        for (int jj = 0; jj < 2; jj++) {
            const int n = n0 + tx * 8 + jj * 4;
            float4 v;
            v.x = silu_f(av[jj * 4 + 0]); v.y = silu_f(av[jj * 4 + 1]);
            v.z = silu_f(av[jj * 4 + 2]); v.w = silu_f(av[jj * 4 + 3]);
            *(float4*)(Out + (long)m * N + n) = v;
        }
    }
}

// ---------------- deformable sampling: softmax(4) + bilinear gather + weighted sum ----------------
// one warp per (l, head); lane = dh channel. grid = (L, B), block = 256 (8 warps = 8 heads)
__global__ __launch_bounds__(256)
void sample_k(const float* __restrict__ bbox)
{
    const int l = blockIdx.x, b = blockIdx.y;
    const int h = threadIdx.x >> 5, lane = threadIdx.x & 31;
    const long bl = (long)b * 4096 + l;
    const float* offp = g_off + bl * 64 + h * 8;
    const float* awp  = g_aw  + bl * 32 + h * 4;
    const float bx = bbox[bl * 2 + 0] * 64.f - 0.5f;
    const float by = bbox[bl * 2 + 1] * 64.f - 0.5f;

    const float a0 = awp[0], a1 = awp[1], a2 = awp[2], a3 = awp[3];
    const float mx = fmaxf(fmaxf(a0, a1), fmaxf(a2, a3));
    const float e0 = __expf(a0 - mx), e1 = __expf(a1 - mx);
    const float e2 = __expf(a2 - mx), e3 = __expf(a3 - mx);
    const float inv = 1.f / (e0 + e1 + e2 + e3);
    float ew[4] = { e0 * inv, e1 * inv, e2 * inv, e3 * inv };

    const float* valb = g_val + (long)b * (4096L * 256) + h * 32 + lane;
    float acc = 0.f;
#pragma unroll
    for (int p = 0; p < 4; p++) {
        const float gx = bx + offp[p * 2 + 0];
        const float gy = by + offp[p * 2 + 1];
        const float fx = floorf(gx), fy = floorf(gy);
        const int x0 = (int)fx, y0 = (int)fy;
        const float wx1 = gx - fx, wy1 = gy - fy;
        const float wx0 = 1.f - wx1, wy0 = 1.f - wy1;
        const bool vx0 = (unsigned)x0 < 64u, vx1 = (unsigned)(x0 + 1) < 64u;
        const bool vy0 = (unsigned)y0 < 64u, vy1 = (unsigned)(y0 + 1) < 64u;
        float v = 0.f;
        if (vy0) {
            const float* row = valb + ((long)y0 << 6) * 256;
            if (vx0) v += wx0 * wy0 * row[(long)x0 * 256];
            if (vx1) v += wx1 * wy0 * row[(long)(x0 + 1) * 256];
        }
        if (vy1) {
            const float* row = valb + ((long)(y0 + 1) << 6) * 256;
            if (vx0) v += wx0 * wy1 * row[(long)x0 * 256];
            if (vx1) v += wx1 * wy1 * row[(long)(x0 + 1) * 256];
        }
        acc += ew[p] * v;
    }
    g_smp[bl * 256 + h * 32 + lane] = acc;
}

// ---------------- launch ----------------
extern "C" void kernel_launch(void* const* d_in, const int* in_sizes, int n_in,
                              void* d_out, int out_size)
{
    const float* x       = (const float*)d_in[0];
    const float* bbox    = (const float*)d_in[1];
    // d_in[2] = value_shapes (constants [64,64]) — unused
    const float* cv1_w   = (const float*)d_in[3];
    const float* m0c1    = (const float*)d_in[4];
    const float* m0c2    = (const float*)d_in[5];
    const float* m1c1    = (const float*)d_in[6];
    const float* m1c2    = (const float*)d_in[7];
    const float* vproj_w = (const float*)d_in[8];
    const float* vproj_b = (const float*)d_in[9];
    const float* off_w   = (const float*)d_in[10];
    const float* off_b   = (const float*)d_in[11];
    const float* aw_w    = (const float*)d_in[12];
    const float* aw_b    = (const float*)d_in[13];
    const float* out_w   = (const float*)d_in[14];
    const float* out_b   = (const float*)d_in[15];
    const float* cv2_w   = (const float*)d_in[16];
    float* out = (float*)d_out;

    float *p_y0, *p_t, *p_b1, *p_b2, *p_val, *p_off, *p_aw, *p_smp, *p_at;
    cudaGetSymbolAddress((void**)&p_y0,  g_y0);
    cudaGetSymbolAddress((void**)&p_t,   g_t);
    cudaGetSymbolAddress((void**)&p_b1,  g_b1);
    cudaGetSymbolAddress((void**)&p_b2,  g_b2);
    cudaGetSymbolAddress((void**)&p_val, g_val);
    cudaGetSymbolAddress((void**)&p_off, g_off);
    cudaGetSymbolAddress((void**)&p_aw,  g_aw);
    cudaGetSymbolAddress((void**)&p_smp, g_smp);
    cudaGetSymbolAddress((void**)&p_at,  g_at);

    dim3 blk(256);

    // cv1: y0 = silu(W[512,512] @ x[b])   C[co, p]
    gemm_k<false, false, 1, 0><<<dim3(32, 4, NB), blk>>>(
        cv1_w, x, nullptr, p_y0, 512, 4096, 512, 0L, 512L * 4096, 512L * 4096);

    // conv3 chain: b -> t -> b1 -> t -> b2
    conv3_k<<<dim3(32, 2, NB), blk>>>(p_y0 + 256L * 4096, m0c1, p_t,  512L * 4096, 256L * 4096);
    conv3_k<<<dim3(32, 2, NB), blk>>>(p_t,                m0c2, p_b1, 256L * 4096, 256L * 4096);
    conv3_k<<<dim3(32, 2, NB), blk>>>(p_b1,               m1c1, p_t,  256L * 4096, 256L * 4096);
    conv3_k<<<dim3(32, 2, NB), blk>>>(p_t,                m1c2, p_b2, 256L * 4096, 256L * 4096);

    // value = q @ vproj_w + b  (q[l,c] = b2[c,l] -> TA)   [B,L,256]
    gemm_k<true, false, 0, 1><<<dim3(2, 32, NB), blk>>>(
        p_b2, vproj_w, vproj_b, p_val, 4096, 256, 256, 256L * 4096, 0L, 4096L * 256);

    // off = q @ off_w + b   [B,L,64]
    gemm_k<true, false, 0, 1><<<dim3(1, 32, NB), blk>>>(
        p_b2, off_w, off_b, p_off, 4096, 64, 256, 256L * 4096, 0L, 4096L * 64);

    // aw logits = q @ aw_w + b   [B,L,32]
    gemm_k<true, false, 0, 1><<<dim3(1, 32, NB), blk>>>(
        p_b2, aw_w, aw_b, p_aw, 4096, 32, 256, 256L * 4096, 0L, 4096L * 32);

    // softmax + bilinear sampling -> g_smp [B,L,256]
    sample_k<<<dim3(4096, NB), blk>>>(bbox);

    // attn^T = out_w^T @ samp^T + out_b   ->  g_at [B,D,L]
    gemm_k<true, true, 0, 2><<<dim3(32, 2, NB), blk>>>(
        out_w, p_smp, out_b, p_at, 256, 4096, 256, 0L, 4096L * 256, 256L * 4096);

    // cv2 over virtual concat -> d_out [B,512,HW]
    cv2_k<<<dim3(32, 4, NB), blk>>>(cv2_w, out);
}

// round 10
// speedup vs baseline: 2.2530x; 2.0697x over previous
#include <cuda_runtime.h>
#include <cstdint>

// ---------------- problem constants ----------------
// B=8, C1=512, C=256, D=256, NH=8, NP=4, NL=1, H=W=64, L=4096
#define NB 8

// ---------------- scratch buffers (device globals; no allocation) ----------------
__device__ float g_y0 [8L*512*4096];  // cv1 output  [B,512,HW]  (a = ch 0-255, b = ch 256-511)
__device__ float g_t  [8L*256*4096];  // conv temp   [B,256,HW]
__device__ float g_b1 [8L*256*4096];
__device__ float g_b2 [8L*256*4096];
__device__ float g_val[8L*4096*256];  // value       [B,L,D]
__device__ float g_off[8L*4096*64];   // offsets     [B,L,64]
__device__ float g_aw [8L*4096*32];   // attn logits [B,L,32]
__device__ float g_smp[8L*4096*256];  // sampled     [B,L,D]
__device__ float g_at [8L*256*4096];  // attn out    [B,D,L]  (transposed for concat)

static __device__ __forceinline__ float silu_f(float x) {
    return x / (1.0f + __expf(-x));
}

// ---------------- bf16 hi/lo split: pack 8 floats -> 4+4 b32 ----------------
__device__ __forceinline__ void cvt8(float4 a, float4 b, uint4& hp, uint4& lp) {
    float f[8] = { a.x, a.y, a.z, a.w, b.x, b.y, b.z, b.w };
    uint32_t* h = (uint32_t*)&hp;
    uint32_t* l = (uint32_t*)&lp;
#pragma unroll
    for (int i = 0; i < 4; i++) {
        uint32_t u0 = __float_as_uint(f[2 * i]);
        uint32_t u1 = __float_as_uint(f[2 * i + 1]);
        h[i] = __byte_perm(u0, u1, 0x7632);
        float l0 = f[2 * i]     - __uint_as_float(u0 & 0xffff0000u);
        float l1 = f[2 * i + 1] - __uint_as_float(u1 & 0xffff0000u);
        l[i] = __byte_perm(__float_as_uint(l0), __float_as_uint(l1), 0x7632);
    }
}

// ---------------- tensor-core primitives (sm_80-era PTX, valid at compute_103) ----------------
__device__ __forceinline__ uint32_t smem_u32(const void* p) {
    uint32_t a;
    asm("{ .reg .u64 t; cvta.to.shared.u64 t, %1; cvt.u32.u64 %0, t; }" : "=r"(a) : "l"(p));
    return a;
}
__device__ __forceinline__ void ldsm_x4(uint32_t* r, uint32_t addr) {
    asm volatile("ldmatrix.sync.aligned.m8n8.x4.shared.b16 {%0,%1,%2,%3}, [%4];"
        : "=r"(r[0]), "=r"(r[1]), "=r"(r[2]), "=r"(r[3]) : "r"(addr));
}
__device__ __forceinline__ void ldsm_x2t(uint32_t* r, uint32_t addr) {
    asm volatile("ldmatrix.sync.aligned.m8n8.x2.trans.shared.b16 {%0,%1}, [%2];"
        : "=r"(r[0]), "=r"(r[1]) : "r"(addr));
}
__device__ __forceinline__ void mma16816(float* d, const uint32_t* a, const uint32_t* b) {
    asm volatile("mma.sync.aligned.m16n8k16.row.col.f32.bf16.bf16.f32 "
        "{%0,%1,%2,%3}, {%4,%5,%6,%7}, {%8,%9}, {%0,%1,%2,%3};"
        : "+f"(d[0]), "+f"(d[1]), "+f"(d[2]), "+f"(d[3])
        : "r"(a[0]), "r"(a[1]), "r"(a[2]), "r"(a[3]), "r"(b[0]), "r"(b[1]));
}

// ---------------- tensor-core conv-family GEMM ----------------
// C[M,4096] = silu(W[M,K] @ Bmat[K,4096]) channel-major, tile 128x128x32, 8 warps @ 64x32
// MODE 0: cv1   B[k][n] = In[k*4096+n]
// MODE 1: conv3 B[k][n] = implicit im2col (k = ci*9 + ky*3 + kx) from channel-major In
// MODE 2: cv2   B[k][n] = virtual concat [y0(512) | b1(256) | b2(256) | at(256)]
#define AP 40    // A row pad: 32+8 bf16  (80B stride -> conflict-free LDSM)
#define BP 136   // B row pad: 128+8 bf16 (272B stride -> conflict-free LDSM)

template<int MODE>
__global__ __launch_bounds__(256, 1)
void tgemm_k(const float* __restrict__ Wt, const float* __restrict__ In,
             float* __restrict__ Out, int K, long sIn, long sOut)
{
    __shared__ __align__(16) uint16_t sAh[128 * AP];
    __shared__ __align__(16) uint16_t sAl[128 * AP];
    __shared__ __align__(16) uint16_t sBh[32 * BP];
    __shared__ __align__(16) uint16_t sBl[32 * BP];

    const int tid = threadIdx.x, wid = tid >> 5, lane = tid & 31;
    const int wm = wid & 1, wn = wid >> 1;          // warp grid 2 (m) x 4 (n)
    const int bz = blockIdx.z;
    const int n0 = blockIdx.x * 128;
    const int m0 = blockIdx.y * 128;
    if (MODE != 2) In += (long)bz * sIn;
    Out += (long)bz * sOut;

    // A-load role: row = tid>>1 (0..127), kh = (tid&1)*16
    const int arow = tid >> 1, akh = (tid & 1) * 16;
    // B-load role: row = tid>>3 (0..31), cg = (tid&7)*16
    const int brow = tid >> 3, bcg = (tid & 7) * 16;

    float rA[16], rB[16];

    auto loadA = [&](int k0) {
        const float* src = Wt + (long)(m0 + arow) * K + k0 + akh;
#pragma unroll
        for (int c = 0; c < 4; c++) *(float4*)(rA + 4 * c) = ((const float4*)src)[c];
    };
    auto loadB = [&](int k0) {
        const int k = k0 + brow;
        if (MODE == 0) {
            const float* src = In + (long)k * 4096 + n0 + bcg;
#pragma unroll
            for (int c = 0; c < 4; c++) *(float4*)(rB + 4 * c) = ((const float4*)src)[c];
        } else if (MODE == 1) {
            const int ci = k / 9, r = k - ci * 9;
            const int ky = r / 3 - 1, kx = (r - (r / 3) * 3) - 1;
            const float* inC = In + (long)ci * 4096;
#pragma unroll
            for (int j = 0; j < 16; j++) {
                const int n = n0 + bcg + j;
                const int y = (n >> 6) + ky, x = (n & 63) + kx;
                rB[j] = (((unsigned)y < 64u) && ((unsigned)x < 64u)) ? inC[(y << 6) + x] : 0.f;
            }
        } else {
            const float* src;
            if (k < 512)       src = g_y0 + (long)bz * (512L * 4096) + (long)k * 4096;
            else if (k < 768)  src = g_b1 + (long)bz * (256L * 4096) + (long)(k - 512) * 4096;
            else if (k < 1024) src = g_b2 + (long)bz * (256L * 4096) + (long)(k - 768) * 4096;
            else               src = g_at + (long)bz * (256L * 4096) + (long)(k - 1024) * 4096;
            src += n0 + bcg;
#pragma unroll
            for (int c = 0; c < 4; c++) *(float4*)(rB + 4 * c) = ((const float4*)src)[c];
        }
    };

    float acc[4][4][4];
#pragma unroll
    for (int i = 0; i < 4; i++)
#pragma unroll
        for (int j = 0; j < 4; j++)
#pragma unroll
            for (int c = 0; c < 4; c++) acc[i][j][c] = 0.f;

    const uint32_t uAh = smem_u32(sAh), uAl = smem_u32(sAl);
    const uint32_t uBh = smem_u32(sBh), uBl = smem_u32(sBl);

    const int nkt = K / 32;
    loadA(0); loadB(0);

    for (int kt = 0; kt < nkt; kt++) {
        // ---- convert + store staged tile
        {
            uint4 hp, lp;
            cvt8(*(float4*)rA, *(float4*)(rA + 4), hp, lp);
            *(uint4*)&sAh[arow * AP + akh] = hp;
            *(uint4*)&sAl[arow * AP + akh] = lp;
            cvt8(*(float4*)(rA + 8), *(float4*)(rA + 12), hp, lp);
            *(uint4*)&sAh[arow * AP + akh + 8] = hp;
            *(uint4*)&sAl[arow * AP + akh + 8] = lp;
            cvt8(*(float4*)rB, *(float4*)(rB + 4), hp, lp);
            *(uint4*)&sBh[brow * BP + bcg] = hp;
            *(uint4*)&sBl[brow * BP + bcg] = lp;
            cvt8(*(float4*)(rB + 8), *(float4*)(rB + 12), hp, lp);
            *(uint4*)&sBh[brow * BP + bcg + 8] = hp;
            *(uint4*)&sBl[brow * BP + bcg + 8] = lp;
        }
        __syncthreads();
        if (kt + 1 < nkt) { loadA((kt + 1) * 32); loadB((kt + 1) * 32); }   // prefetch overlaps MMA

#pragma unroll
        for (int ks = 0; ks < 2; ks++) {
            uint32_t Ah[4][4], Al[4][4], Bh[4][2], Bl[4][2];
            const int karow = wm * 64 + (lane & 15);
            const int kacol = ks * 16 + (lane >> 4) * 8;
#pragma unroll
            for (int mi = 0; mi < 4; mi++) {
                const uint32_t off = (uint32_t)((karow + mi * 16) * AP + kacol) * 2;
                ldsm_x4(Ah[mi], uAh + off);
                ldsm_x4(Al[mi], uAl + off);
            }
            const int kbrow = ks * 16 + (lane & 15);
#pragma unroll
            for (int nj = 0; nj < 4; nj++) {
                const uint32_t off = (uint32_t)(kbrow * BP + wn * 32 + nj * 8) * 2;
                ldsm_x2t(Bh[nj], uBh + off);
                ldsm_x2t(Bl[nj], uBl + off);
            }
#pragma unroll
            for (int mi = 0; mi < 4; mi++)
#pragma unroll
                for (int nj = 0; nj < 4; nj++) {
                    mma16816(acc[mi][nj], Ah[mi], Bh[nj]);
                    mma16816(acc[mi][nj], Ah[mi], Bl[nj]);
                    mma16816(acc[mi][nj], Al[mi], Bh[nj]);
                }
        }
        __syncthreads();
    }

    // ---- epilogue: silu, direct channel-major stores (float2 per fragment row)
    const int er = lane >> 2, ec = (lane & 3) * 2;
#pragma unroll
    for (int mi = 0; mi < 4; mi++) {
        const int r = m0 + wm * 64 + mi * 16 + er;
#pragma unroll
        for (int nj = 0; nj < 4; nj++) {
            const int c = n0 + wn * 32 + nj * 8 + ec;
            float2 v0, v1;
            v0.x = silu_f(acc[mi][nj][0]); v0.y = silu_f(acc[mi][nj][1]);
            v1.x = silu_f(acc[mi][nj][2]); v1.y = silu_f(acc[mi][nj][3]);
            *(float2*)(Out + (long)r * 4096 + c)       = v0;
            *(float2*)(Out + (long)(r + 8) * 4096 + c) = v1;
        }
    }
}

// ---------------- fp32x2 GEMM (attention projections; round-2 proven path) ----------------
typedef unsigned long long u64;
static __device__ __forceinline__ u64 dup2(float x) {
    u64 r; asm("mov.b64 %0, {%1, %1};" : "=l"(r) : "r"(__float_as_uint(x))); return r;
}
static __device__ __forceinline__ void fma2(u64& d, u64 a, u64 b) {
    asm("fma.rn.f32x2 %0, %1, %2, %3;" : "=l"(d) : "l"(a), "l"(b), "l"(d));
}
static __device__ __forceinline__ float2 unpk2(u64 v) {
    float2 r; asm("mov.b64 {%0, %1}, %2;" : "=f"(r.x), "=f"(r.y) : "l"(v)); return r;
}

// TA: a(m,k)=A[k*M+m] else A[m*K+k].  TB: b(k,n)=B[n*K+k] else B[k*N+n].
// BIAS: 1 bias[n], 2 bias[m]
template<bool TA, bool TB, int BIAS>
__global__ __launch_bounds__(256, 2)
void gemm_k(const float* __restrict__ A, const float* __restrict__ Bm,
            const float* __restrict__ bias, float* __restrict__ Cm,
            int M, int N, int K, long sA, long sB, long sC)
{
    const int bz = blockIdx.z;
    A  += (long)bz * sA;
    Bm += (long)bz * sB;
    Cm += (long)bz * sC;
    const int n0 = blockIdx.x * 128;
    const int m0 = blockIdx.y * 128;
    __shared__ float As[8][128];
    __shared__ float Bs[8][128];
    const int tid = threadIdx.x;
    const int tx = tid & 15, ty = tid >> 4;
    u64 acc2[8][4];
#pragma unroll
    for (int i = 0; i < 8; i++)
#pragma unroll
        for (int j = 0; j < 4; j++) acc2[i][j] = 0ull;

    for (int k0 = 0; k0 < K; k0 += 8) {
        if (TA) {
            const int i = (tid & 31) * 4, kk = tid >> 5;
            *(float4*)&As[kk][i] = *(const float4*)(A + (long)(k0 + kk) * M + m0 + i);
        } else {
            const int mi = tid >> 1, kk4 = (tid & 1) * 4;
            float4 v = *(const float4*)(A + (long)(m0 + mi) * K + k0 + kk4);
            As[kk4 + 0][mi] = v.x; As[kk4 + 1][mi] = v.y;
            As[kk4 + 2][mi] = v.z; As[kk4 + 3][mi] = v.w;
        }
        if (TB) {
            const int ni = tid >> 1, kk4 = (tid & 1) * 4;
            float4 v = make_float4(0.f, 0.f, 0.f, 0.f);
            if (n0 + ni < N) v = *(const float4*)(Bm + (long)(n0 + ni) * K + k0 + kk4);
            Bs[kk4 + 0][ni] = v.x; Bs[kk4 + 1][ni] = v.y;
            Bs[kk4 + 2][ni] = v.z; Bs[kk4 + 3][ni] = v.w;
        } else {
            const int j = (tid & 31) * 4, kk = tid >> 5;
            float4 v = make_float4(0.f, 0.f, 0.f, 0.f);
            if (n0 + j < N) v = *(const float4*)(Bm + (long)(k0 + kk) * N + n0 + j);
            *(float4*)&Bs[kk][j] = v;
        }
        __syncthreads();
#pragma unroll
        for (int kk = 0; kk < 8; kk++) {
            float a[8];
            *(float4*)(a)     = *(float4*)&As[kk][ty * 8];
            *(float4*)(a + 4) = *(float4*)&As[kk][ty * 8 + 4];
            ulonglong2 t0 = *(const ulonglong2*)&Bs[kk][tx * 8];
            ulonglong2 t1 = *(const ulonglong2*)&Bs[kk][tx * 8 + 4];
            u64 b2[4] = { t0.x, t0.y, t1.x, t1.y };
            u64 a2[8];
#pragma unroll
            for (int i = 0; i < 8; i++) a2[i] = dup2(a[i]);
#pragma unroll
            for (int i = 0; i < 8; i++)
#pragma unroll
                for (int j = 0; j < 4; j++) fma2(acc2[i][j], a2[i], b2[j]);
        }
        __syncthreads();
    }
#pragma unroll
    for (int i = 0; i < 8; i++) {
        const int m = m0 + ty * 8 + i;
        const float bmv = (BIAS == 2) ? bias[m] : 0.f;
        float av[8];
#pragma unroll
        for (int j = 0; j < 4; j++) {
            float2 p = unpk2(acc2[i][j]);
            av[2 * j] = p.x; av[2 * j + 1] = p.y;
        }
#pragma unroll
        for (int jj = 0; jj < 2; jj++) {
            const int n = n0 + tx * 8 + jj * 4;
            if (n < N) {
                float4 v;
                v.x = av[jj * 4 + 0]; v.y = av[jj * 4 + 1];
                v.z = av[jj * 4 + 2]; v.w = av[jj * 4 + 3];
                if (BIAS == 1) {
                    v.x += bias[n]; v.y += bias[n + 1]; v.z += bias[n + 2]; v.w += bias[n + 3];
                } else {
                    v.x += bmv; v.y += bmv; v.z += bmv; v.w += bmv;
                }
                *(float4*)(Cm + (long)m * N + n) = v;
            }
        }
    }
}

// ---------------- deformable sampling ----------------
__global__ __launch_bounds__(256)
void sample_k(const float* __restrict__ bbox)
{
    const int l = blockIdx.x, b = blockIdx.y;
    const int h = threadIdx.x >> 5, lane = threadIdx.x & 31;
    const long bl = (long)b * 4096 + l;
    const float* offp = g_off + bl * 64 + h * 8;
    const float* awp  = g_aw  + bl * 32 + h * 4;
    const float bx = bbox[bl * 2 + 0] * 64.f - 0.5f;
    const float by = bbox[bl * 2 + 1] * 64.f - 0.5f;

    const float a0 = awp[0], a1 = awp[1], a2 = awp[2], a3 = awp[3];
    const float mx = fmaxf(fmaxf(a0, a1), fmaxf(a2, a3));
    const float e0 = __expf(a0 - mx), e1 = __expf(a1 - mx);
    const float e2 = __expf(a2 - mx), e3 = __expf(a3 - mx);
    const float inv = 1.f / (e0 + e1 + e2 + e3);
    float ew[4] = { e0 * inv, e1 * inv, e2 * inv, e3 * inv };

    const float* valb = g_val + (long)b * (4096L * 256) + h * 32 + lane;
    float acc = 0.f;
#pragma unroll
    for (int p = 0; p < 4; p++) {
        const float gx = bx + offp[p * 2 + 0];
        const float gy = by + offp[p * 2 + 1];
        const float fx = floorf(gx), fy = floorf(gy);
        const int x0 = (int)fx, y0 = (int)fy;
        const float wx1 = gx - fx, wy1 = gy - fy;
        const float wx0 = 1.f - wx1, wy0 = 1.f - wy1;
        const bool vx0 = (unsigned)x0 < 64u, vx1 = (unsigned)(x0 + 1) < 64u;
        const bool vy0 = (unsigned)y0 < 64u, vy1 = (unsigned)(y0 + 1) < 64u;
        float v = 0.f;
        if (vy0) {
            const float* row = valb + ((long)y0 << 6) * 256;
            if (vx0) v += wx0 * wy0 * row[(long)x0 * 256];
            if (vx1) v += wx1 * wy0 * row[(long)(x0 + 1) * 256];
        }
        if (vy1) {
            const float* row = valb + ((long)(y0 + 1) << 6) * 256;
            if (vx0) v += wx0 * wy1 * row[(long)x0 * 256];
            if (vx1) v += wx1 * wy1 * row[(long)(x0 + 1) * 256];
        }
        acc += ew[p] * v;
    }
    g_smp[bl * 256 + h * 32 + lane] = acc;
}

// ---------------- launch ----------------
extern "C" void kernel_launch(void* const* d_in, const int* in_sizes, int n_in,
                              void* d_out, int out_size)
{
    const float* x       = (const float*)d_in[0];
    const float* bbox    = (const float*)d_in[1];
    const float* cv1_w   = (const float*)d_in[3];
    const float* m0c1    = (const float*)d_in[4];
    const float* m0c2    = (const float*)d_in[5];
    const float* m1c1    = (const float*)d_in[6];
    const float* m1c2    = (const float*)d_in[7];
    const float* vproj_w = (const float*)d_in[8];
    const float* vproj_b = (const float*)d_in[9];
    const float* off_w   = (const float*)d_in[10];
    const float* off_b   = (const float*)d_in[11];
    const float* aw_w    = (const float*)d_in[12];
    const float* aw_b    = (const float*)d_in[13];
    const float* out_w   = (const float*)d_in[14];
    const float* out_b   = (const float*)d_in[15];
    const float* cv2_w   = (const float*)d_in[16];
    float* out = (float*)d_out;

    float *p_y0, *p_t, *p_b1, *p_b2, *p_val, *p_off, *p_aw, *p_smp, *p_at;
    cudaGetSymbolAddress((void**)&p_y0,  g_y0);
    cudaGetSymbolAddress((void**)&p_t,   g_t);
    cudaGetSymbolAddress((void**)&p_b1,  g_b1);
    cudaGetSymbolAddress((void**)&p_b2,  g_b2);
    cudaGetSymbolAddress((void**)&p_val, g_val);
    cudaGetSymbolAddress((void**)&p_off, g_off);
    cudaGetSymbolAddress((void**)&p_aw,  g_aw);
    cudaGetSymbolAddress((void**)&p_smp, g_smp);
    cudaGetSymbolAddress((void**)&p_at,  g_at);

    dim3 blk(256);

    // cv1: y0 = silu(W[512,512] @ x)  [B,512,4096]
    tgemm_k<0><<<dim3(32, 4, NB), blk>>>(cv1_w, x, p_y0, 512, 512L * 4096, 512L * 4096);

    // conv3 chain: b -> t -> b1 -> t -> b2  (tensor-core implicit im2col)
    tgemm_k<1><<<dim3(32, 2, NB), blk>>>(m0c1, p_y0 + 256L * 4096, p_t,  2304, 512L * 4096, 256L * 4096);
    tgemm_k<1><<<dim3(32, 2, NB), blk>>>(m0c2, p_t,                p_b1, 2304, 256L * 4096, 256L * 4096);
    tgemm_k<1><<<dim3(32, 2, NB), blk>>>(m1c1, p_b1,               p_t,  2304, 256L * 4096, 256L * 4096);
    tgemm_k<1><<<dim3(32, 2, NB), blk>>>(m1c2, p_t,                p_b2, 2304, 256L * 4096, 256L * 4096);

    // value = q @ vproj_w + b  (q[l,c] = b2[c,l] -> TA)   [B,L,256]
    gemm_k<true, false, 1><<<dim3(2, 32, NB), blk>>>(
        p_b2, vproj_w, vproj_b, p_val, 4096, 256, 256, 256L * 4096, 0L, 4096L * 256);

    // off = q @ off_w + b   [B,L,64]
    gemm_k<true, false, 1><<<dim3(1, 32, NB), blk>>>(
        p_b2, off_w, off_b, p_off, 4096, 64, 256, 256L * 4096, 0L, 4096L * 64);

    // aw logits = q @ aw_w + b   [B,L,32]
    gemm_k<true, false, 1><<<dim3(1, 32, NB), blk>>>(
        p_b2, aw_w, aw_b, p_aw, 4096, 32, 256, 256L * 4096, 0L, 4096L * 32);

    // softmax + bilinear sampling -> g_smp [B,L,256]
    sample_k<<<dim3(4096, NB), blk>>>(bbox);

    // attn^T = out_w^T @ samp^T + out_b   ->  g_at [B,D,L]
    gemm_k<true, true, 2><<<dim3(32, 2, NB), blk>>>(
        out_w, p_smp, out_b, p_at, 256, 4096, 256, 0L, 4096L * 256, 256L * 4096);

    // cv2 over virtual concat -> d_out [B,512,4096]
    tgemm_k<2><<<dim3(32, 4, NB), blk>>>(cv2_w, nullptr, out, 1280, 0L, 512L * 4096);
}

// round 14
// speedup vs baseline: 2.3779x; 1.0554x over previous
#include <cuda_runtime.h>
#include <cstdint>

// ---------------- problem constants ----------------
// B=8, C1=512, C=256, D=256, NH=8, NP=4, NL=1, H=W=64, L=4096
#define NB 8

// ---------------- scratch buffers (device globals; no allocation) ----------------
__device__ float g_y0 [8L*512*4096];  // cv1 output  [B,512,HW]  (a = ch 0-255, b = ch 256-511)
__device__ float g_t  [8L*256*4096];  // conv temp   [B,256,HW]
__device__ float g_b1 [8L*256*4096];
__device__ float g_b2 [8L*256*4096];
__device__ float g_val[8L*4096*256];  // value       [B,L,D]
__device__ float g_off[8L*4096*64];   // offsets     [B,L,64]
__device__ float g_aw [8L*4096*32];   // attn logits [B,L,32]
__device__ float g_smp[8L*4096*256];  // sampled     [B,L,D]
__device__ float g_at [8L*256*4096];  // attn out    [B,D,L]  (transposed for concat)

static __device__ __forceinline__ float silu_f(float x) {
    return x / (1.0f + __expf(-x));
}

// ---------------- bf16 hi/lo split: pack 8 floats -> 4+4 b32 ----------------
__device__ __forceinline__ void cvt8(float4 a, float4 b, uint4& hp, uint4& lp) {
    float f[8] = { a.x, a.y, a.z, a.w, b.x, b.y, b.z, b.w };
    uint32_t* h = (uint32_t*)&hp;
    uint32_t* l = (uint32_t*)&lp;
#pragma unroll
    for (int i = 0; i < 4; i++) {
        uint32_t u0 = __float_as_uint(f[2 * i]);
        uint32_t u1 = __float_as_uint(f[2 * i + 1]);
        h[i] = __byte_perm(u0, u1, 0x7632);
        float l0 = f[2 * i]     - __uint_as_float(u0 & 0xffff0000u);
        float l1 = f[2 * i + 1] - __uint_as_float(u1 & 0xffff0000u);
        l[i] = __byte_perm(__float_as_uint(l0), __float_as_uint(l1), 0x7632);
    }
}

// ---------------- tensor-core primitives (sm_80-era PTX, valid at compute_103) ----------------
__device__ __forceinline__ uint32_t smem_u32(const void* p) {
    uint32_t a;
    asm("{ .reg .u64 t; cvta.to.shared.u64 t, %1; cvt.u32.u64 %0, t; }" : "=r"(a) : "l"(p));
    return a;
}
__device__ __forceinline__ void ldsm_x4(uint32_t* r, uint32_t addr) {
    asm volatile("ldmatrix.sync.aligned.m8n8.x4.shared.b16 {%0,%1,%2,%3}, [%4];"
        : "=r"(r[0]), "=r"(r[1]), "=r"(r[2]), "=r"(r[3]) : "r"(addr));
}
__device__ __forceinline__ void ldsm_x4t(uint32_t* r, uint32_t addr) {
    asm volatile("ldmatrix.sync.aligned.m8n8.x4.trans.shared.b16 {%0,%1,%2,%3}, [%4];"
        : "=r"(r[0]), "=r"(r[1]), "=r"(r[2]), "=r"(r[3]) : "r"(addr));
}
__device__ __forceinline__ void mma16816(float* d, const uint32_t* a, const uint32_t* b) {
    asm volatile("mma.sync.aligned.m16n8k16.row.col.f32.bf16.bf16.f32 "
        "{%0,%1,%2,%3}, {%4,%5,%6,%7}, {%8,%9}, {%0,%1,%2,%3};"
        : "+f"(d[0]), "+f"(d[1]), "+f"(d[2]), "+f"(d[3])
        : "r"(a[0]), "r"(a[1]), "r"(a[2]), "r"(a[3]), "r"(b[0]), "r"(b[1]));
}

// ---------------- tensor-core conv-family GEMM ----------------
// C[M,4096] = silu(W[M,K] @ Bmat[K,4096]) channel-major, tile 128x128x32, 8 warps @ 64x32
// Double-buffered smem staging, ONE __syncthreads per k-tile.
// MODE 0: cv1   B[k][n] = In[k*4096+n]
// MODE 1: conv3 B[k][n] = implicit im2col (k = ci*9 + ky*3 + kx) from channel-major In
// MODE 2: cv2   B[k][n] = virtual concat [y0(512) | b1(256) | b2(256) | at(256)]
#define AP 40    // A row pad: 32+8 bf16  (80B stride -> conflict-free LDSM)
#define BP 136   // B row pad: 128+8 bf16 (272B stride -> conflict-free LDSM)
#define E_AH 0
#define E_AL (128 * AP)
#define E_BH (2 * 128 * AP)
#define E_BL (2 * 128 * AP + 32 * BP)
#define STG_E (2 * 128 * AP + 2 * 32 * BP)     // uint16 elems per stage = 18944
#define SMEM_DB (2 * STG_E * 2)                // bytes = 75776

template<int MODE>
__global__ __launch_bounds__(256, 1)
void tgemm_k(const float* __restrict__ Wt, const float* __restrict__ In,
             float* __restrict__ Out, int K, long sIn, long sOut)
{
    extern __shared__ __align__(16) uint16_t sm[];

    const int tid = threadIdx.x, wid = tid >> 5, lane = tid & 31;
    const int wm = wid & 1, wn = wid >> 1;          // warp grid 2 (m) x 4 (n)
    const int bz = blockIdx.z;
    const int n0 = blockIdx.x * 128;
    const int m0 = blockIdx.y * 128;
    if (MODE != 2) In += (long)bz * sIn;
    Out += (long)bz * sOut;

    // A-load role: row = tid>>1 (0..127), kh = (tid&1)*16
    const int arow = tid >> 1, akh = (tid & 1) * 16;
    // B-load role: row = tid>>3 (0..31), cg = (tid&7)*16
    const int brow = tid >> 3, bcg = (tid & 7) * 16;

    float rA[16], rB[16];

    auto loadA = [&](int k0) {
        const float* src = Wt + (long)(m0 + arow) * K + k0 + akh;
#pragma unroll
        for (int c = 0; c < 4; c++) *(float4*)(rA + 4 * c) = ((const float4*)src)[c];
    };
    auto loadB = [&](int k0) {
        const int k = k0 + brow;
        if (MODE == 0) {
            const float* src = In + (long)k * 4096 + n0 + bcg;
#pragma unroll
            for (int c = 0; c < 4; c++) *(float4*)(rB + 4 * c) = ((const float4*)src)[c];
        } else if (MODE == 1) {
            const int ci = k / 9, r = k - ci * 9;
            const int ky = r / 3 - 1, kx = (r - (r / 3) * 3) - 1;
            const float* inC = In + (long)ci * 4096;
#pragma unroll
            for (int j = 0; j < 16; j++) {
                const int n = n0 + bcg + j;
                const int y = (n >> 6) + ky, x = (n & 63) + kx;
                rB[j] = (((unsigned)y < 64u) && ((unsigned)x < 64u)) ? inC[(y << 6) + x] : 0.f;
            }
        } else {
            const float* src;
            if (k < 512)       src = g_y0 + (long)bz * (512L * 4096) + (long)k * 4096;
            else if (k < 768)  src = g_b1 + (long)bz * (256L * 4096) + (long)(k - 512) * 4096;
            else if (k < 1024) src = g_b2 + (long)bz * (256L * 4096) + (long)(k - 768) * 4096;
            else               src = g_at + (long)bz * (256L * 4096) + (long)(k - 1024) * 4096;
            src += n0 + bcg;
#pragma unroll
            for (int c = 0; c < 4; c++) *(float4*)(rB + 4 * c) = ((const float4*)src)[c];
        }
    };

    float acc[4][4][4];
#pragma unroll
    for (int i = 0; i < 4; i++)
#pragma unroll
        for (int j = 0; j < 4; j++)
#pragma unroll
            for (int c = 0; c < 4; c++) acc[i][j][c] = 0.f;

    const uint32_t u0 = smem_u32(sm);
    const int nkt = K / 32;
    loadA(0); loadB(0);

    for (int kt = 0; kt < nkt; kt++) {
        const int p = kt & 1;
        uint16_t* SAh = sm + p * STG_E + E_AH;
        uint16_t* SAl = sm + p * STG_E + E_AL;
        uint16_t* SBh = sm + p * STG_E + E_BH;
        uint16_t* SBl = sm + p * STG_E + E_BL;

        // ---- convert + store staged tile p
        {
            uint4 hp, lp;
            cvt8(*(float4*)rA, *(float4*)(rA + 4), hp, lp);
            *(uint4*)&SAh[arow * AP + akh] = hp;
            *(uint4*)&SAl[arow * AP + akh] = lp;
            cvt8(*(float4*)(rA + 8), *(float4*)(rA + 12), hp, lp);
            *(uint4*)&SAh[arow * AP + akh + 8] = hp;
            *(uint4*)&SAl[arow * AP + akh + 8] = lp;
            cvt8(*(float4*)rB, *(float4*)(rB + 4), hp, lp);
            *(uint4*)&SBh[brow * BP + bcg] = hp;
            *(uint4*)&SBl[brow * BP + bcg] = lp;
            cvt8(*(float4*)(rB + 8), *(float4*)(rB + 12), hp, lp);
            *(uint4*)&SBh[brow * BP + bcg + 8] = hp;
            *(uint4*)&SBl[brow * BP + bcg + 8] = lp;
        }
        if (kt + 1 < nkt) { loadA((kt + 1) * 32); loadB((kt + 1) * 32); }   // prefetch
        __syncthreads();   // ONE barrier per tile: STS(p) visible; prior reads of p^1 done

        const uint32_t uAh = u0 + (uint32_t)(p * STG_E + E_AH) * 2;
        const uint32_t uAl = u0 + (uint32_t)(p * STG_E + E_AL) * 2;
        const uint32_t uBh = u0 + (uint32_t)(p * STG_E + E_BH) * 2;
        const uint32_t uBl = u0 + (uint32_t)(p * STG_E + E_BL) * 2;

#pragma unroll
        for (int ks = 0; ks < 2; ks++) {
            uint32_t Ah[4][4], Al[4][4], Bh[4][2], Bl[4][2];
            const int karow = wm * 64 + (lane & 15);
            const int kacol = ks * 16 + (lane >> 4) * 8;
#pragma unroll
            for (int mi = 0; mi < 4; mi++) {
                const uint32_t off = (uint32_t)((karow + mi * 16) * AP + kacol) * 2;
                ldsm_x4(Ah[mi], uAh + off);
                ldsm_x4(Al[mi], uAl + off);
            }
            // B via x4.trans: lanes 0-15 -> rows, lanes 16-31 -> +8 cols
            const int kbrow = ks * 16 + (lane & 15);
            const int bcol  = wn * 32 + ((lane >> 4) & 1) * 8;
#pragma unroll
            for (int njp = 0; njp < 2; njp++) {
                const uint32_t off = (uint32_t)(kbrow * BP + bcol + njp * 16) * 2;
                uint32_t r[4];
                ldsm_x4t(r, uBh + off);
                Bh[2 * njp][0] = r[0]; Bh[2 * njp][1] = r[1];
                Bh[2 * njp + 1][0] = r[2]; Bh[2 * njp + 1][1] = r[3];
                ldsm_x4t(r, uBl + off);
                Bl[2 * njp][0] = r[0]; Bl[2 * njp][1] = r[1];
                Bl[2 * njp + 1][0] = r[2]; Bl[2 * njp + 1][1] = r[3];
            }
#pragma unroll
            for (int mi = 0; mi < 4; mi++)
#pragma unroll
                for (int nj = 0; nj < 4; nj++) {
                    mma16816(acc[mi][nj], Ah[mi], Bh[nj]);
                    mma16816(acc[mi][nj], Ah[mi], Bl[nj]);
                    mma16816(acc[mi][nj], Al[mi], Bh[nj]);
                }
        }
    }

    // ---- epilogue: silu, direct channel-major stores (float2 per fragment row)
    const int er = lane >> 2, ec = (lane & 3) * 2;
#pragma unroll
    for (int mi = 0; mi < 4; mi++) {
        const int r = m0 + wm * 64 + mi * 16 + er;
#pragma unroll
        for (int nj = 0; nj < 4; nj++) {
            const int c = n0 + wn * 32 + nj * 8 + ec;
            float2 v0, v1;
            v0.x = silu_f(acc[mi][nj][0]); v0.y = silu_f(acc[mi][nj][1]);
            v1.x = silu_f(acc[mi][nj][2]); v1.y = silu_f(acc[mi][nj][3]);
            *(float2*)(Out + (long)r * 4096 + c)       = v0;
            *(float2*)(Out + (long)(r + 8) * 4096 + c) = v1;
        }
    }
}

// ---------------- fp32x2 GEMM (attention projections) ----------------
typedef unsigned long long u64;
static __device__ __forceinline__ u64 dup2(float x) {
    u64 r; asm("mov.b64 %0, {%1, %1};" : "=l"(r) : "r"(__float_as_uint(x))); return r;
}
static __device__ __forceinline__ void fma2(u64& d, u64 a, u64 b) {
    asm("fma.rn.f32x2 %0, %1, %2, %3;" : "=l"(d) : "l"(a), "l"(b), "l"(d));
}
static __device__ __forceinline__ float2 unpk2(u64 v) {
    float2 r; asm("mov.b64 {%0, %1}, %2;" : "=f"(r.x), "=f"(r.y) : "l"(v)); return r;
}

// TA: a(m,k)=A[k*M+m] else A[m*K+k].  TB: b(k,n)=B[n*K+k] else B[k*N+n].
// BIAS: 1 bias[n], 2 bias[m]
template<bool TA, bool TB, int BIAS>
__global__ __launch_bounds__(256, 2)
void gemm_k(const float* __restrict__ A, const float* __restrict__ Bm,
            const float* __restrict__ bias, float* __restrict__ Cm,
            int M, int N, int K, long sA, long sB, long sC)
{
    const int bz = blockIdx.z;
    A  += (long)bz * sA;
    Bm += (long)bz * sB;
    Cm += (long)bz * sC;
    const int n0 = blockIdx.x * 128;
    const int m0 = blockIdx.y * 128;
    __shared__ float As[8][128];
    __shared__ float Bs[8][128];
    const int tid = threadIdx.x;
    const int tx = tid & 15, ty = tid >> 4;
    u64 acc2[8][4];
#pragma unroll
    for (int i = 0; i < 8; i++)
#pragma unroll
        for (int j = 0; j < 4; j++) acc2[i][j] = 0ull;

    for (int k0 = 0; k0 < K; k0 += 8) {
        if (TA) {
            const int i = (tid & 31) * 4, kk = tid >> 5;
            *(float4*)&As[kk][i] = *(const float4*)(A + (long)(k0 + kk) * M + m0 + i);
        } else {
            const int mi = tid >> 1, kk4 = (tid & 1) * 4;
            float4 v = *(const float4*)(A + (long)(m0 + mi) * K + k0 + kk4);
            As[kk4 + 0][mi] = v.x; As[kk4 + 1][mi] = v.y;
            As[kk4 + 2][mi] = v.z; As[kk4 + 3][mi] = v.w;
        }
        if (TB) {
            const int ni = tid >> 1, kk4 = (tid & 1) * 4;
            float4 v = make_float4(0.f, 0.f, 0.f, 0.f);
            if (n0 + ni < N) v = *(const float4*)(Bm + (long)(n0 + ni) * K + k0 + kk4);
            Bs[kk4 + 0][ni] = v.x; Bs[kk4 + 1][ni] = v.y;
            Bs[kk4 + 2][ni] = v.z; Bs[kk4 + 3][ni] = v.w;
        } else {
            const int j = (tid & 31) * 4, kk = tid >> 5;
            float4 v = make_float4(0.f, 0.f, 0.f, 0.f);
            if (n0 + j < N) v = *(const float4*)(Bm + (long)(k0 + kk) * N + n0 + j);
            *(float4*)&Bs[kk][j] = v;
        }
        __syncthreads();
#pragma unroll
        for (int kk = 0; kk < 8; kk++) {
            float a[8];
            *(float4*)(a)     = *(float4*)&As[kk][ty * 8];
            *(float4*)(a + 4) = *(float4*)&As[kk][ty * 8 + 4];
            ulonglong2 t0 = *(const ulonglong2*)&Bs[kk][tx * 8];
            ulonglong2 t1 = *(const ulonglong2*)&Bs[kk][tx * 8 + 4];
            u64 b2[4] = { t0.x, t0.y, t1.x, t1.y };
            u64 a2[8];
#pragma unroll
            for (int i = 0; i < 8; i++) a2[i] = dup2(a[i]);
#pragma unroll
            for (int i = 0; i < 8; i++)
#pragma unroll
                for (int j = 0; j < 4; j++) fma2(acc2[i][j], a2[i], b2[j]);
        }
        __syncthreads();
    }
#pragma unroll
    for (int i = 0; i < 8; i++) {
        const int m = m0 + ty * 8 + i;
        const float bmv = (BIAS == 2) ? bias[m] : 0.f;
        float av[8];
#pragma unroll
        for (int j = 0; j < 4; j++) {
            float2 p = unpk2(acc2[i][j]);
            av[2 * j] = p.x; av[2 * j + 1] = p.y;
        }
#pragma unroll
        for (int jj = 0; jj < 2; jj++) {
            const int n = n0 + tx * 8 + jj * 4;
            if (n < N) {
                float4 v;
                v.x = av[jj * 4 + 0]; v.y = av[jj * 4 + 1];
                v.z = av[jj * 4 + 2]; v.w = av[jj * 4 + 3];
                if (BIAS == 1) {
                    v.x += bias[n]; v.y += bias[n + 1]; v.z += bias[n + 2]; v.w += bias[n + 3];
                } else {
                    v.x += bmv; v.y += bmv; v.z += bmv; v.w += bmv;
                }
                *(float4*)(Cm + (long)m * N + n) = v;
            }
        }
    }
}

// ---------------- deformable sampling ----------------
__global__ __launch_bounds__(256)
void sample_k(const float* __restrict__ bbox)
{
    const int l = blockIdx.x, b = blockIdx.y;
    const int h = threadIdx.x >> 5, lane = threadIdx.x & 31;
    const long bl = (long)b * 4096 + l;
    const float* offp = g_off + bl * 64 + h * 8;
    const float* awp  = g_aw  + bl * 32 + h * 4;
    const float bx = bbox[bl * 2 + 0] * 64.f - 0.5f;
    const float by = bbox[bl * 2 + 1] * 64.f - 0.5f;

    const float a0 = awp[0], a1 = awp[1], a2 = awp[2], a3 = awp[3];
    const float mx = fmaxf(fmaxf(a0, a1), fmaxf(a2, a3));
    const float e0 = __expf(a0 - mx), e1 = __expf(a1 - mx);
    const float e2 = __expf(a2 - mx), e3 = __expf(a3 - mx);
    const float inv = 1.f / (e0 + e1 + e2 + e3);
    float ew[4] = { e0 * inv, e1 * inv, e2 * inv, e3 * inv };

    const float* valb = g_val + (long)b * (4096L * 256) + h * 32 + lane;
    float acc = 0.f;
#pragma unroll
    for (int p = 0; p < 4; p++) {
        const float gx = bx + offp[p * 2 + 0];
        const float gy = by + offp[p * 2 + 1];
        const float fx = floorf(gx), fy = floorf(gy);
        const int x0 = (int)fx, y0 = (int)fy;
        const float wx1 = gx - fx, wy1 = gy - fy;
        const float wx0 = 1.f - wx1, wy0 = 1.f - wy1;
        const bool vx0 = (unsigned)x0 < 64u, vx1 = (unsigned)(x0 + 1) < 64u;
        const bool vy0 = (unsigned)y0 < 64u, vy1 = (unsigned)(y0 + 1) < 64u;
        float v = 0.f;
        if (vy0) {
            const float* row = valb + ((long)y0 << 6) * 256;
            if (vx0) v += wx0 * wy0 * row[(long)x0 * 256];
            if (vx1) v += wx1 * wy0 * row[(long)(x0 + 1) * 256];
        }
        if (vy1) {
            const float* row = valb + ((long)(y0 + 1) << 6) * 256;
            if (vx0) v += wx0 * wy1 * row[(long)x0 * 256];
            if (vx1) v += wx1 * wy1 * row[(long)(x0 + 1) * 256];
        }
        acc += ew[p] * v;
    }
    g_smp[bl * 256 + h * 32 + lane] = acc;
}

// ---------------- launch ----------------
extern "C" void kernel_launch(void* const* d_in, const int* in_sizes, int n_in,
                              void* d_out, int out_size)
{
    const float* x       = (const float*)d_in[0];
    const float* bbox    = (const float*)d_in[1];
    const float* cv1_w   = (const float*)d_in[3];
    const float* m0c1    = (const float*)d_in[4];
    const float* m0c2    = (const float*)d_in[5];
    const float* m1c1    = (const float*)d_in[6];
    const float* m1c2    = (const float*)d_in[7];
    const float* vproj_w = (const float*)d_in[8];
    const float* vproj_b = (const float*)d_in[9];
    const float* off_w   = (const float*)d_in[10];
    const float* off_b   = (const float*)d_in[11];
    const float* aw_w    = (const float*)d_in[12];
    const float* aw_b    = (const float*)d_in[13];
    const float* out_w   = (const float*)d_in[14];
    const float* out_b   = (const float*)d_in[15];
    const float* cv2_w   = (const float*)d_in[16];
    float* out = (float*)d_out;

    float *p_y0, *p_t, *p_b1, *p_b2, *p_val, *p_off, *p_aw, *p_smp, *p_at;
    cudaGetSymbolAddress((void**)&p_y0,  g_y0);
    cudaGetSymbolAddress((void**)&p_t,   g_t);
    cudaGetSymbolAddress((void**)&p_b1,  g_b1);
    cudaGetSymbolAddress((void**)&p_b2,  g_b2);
    cudaGetSymbolAddress((void**)&p_val, g_val);
    cudaGetSymbolAddress((void**)&p_off, g_off);
    cudaGetSymbolAddress((void**)&p_aw,  g_aw);
    cudaGetSymbolAddress((void**)&p_smp, g_smp);
    cudaGetSymbolAddress((void**)&p_at,  g_at);

    cudaFuncSetAttribute(tgemm_k<0>, cudaFuncAttributeMaxDynamicSharedMemorySize, SMEM_DB);
    cudaFuncSetAttribute(tgemm_k<1>, cudaFuncAttributeMaxDynamicSharedMemorySize, SMEM_DB);
    cudaFuncSetAttribute(tgemm_k<2>, cudaFuncAttributeMaxDynamicSharedMemorySize, SMEM_DB);

    dim3 blk(256);

    // cv1: y0 = silu(W[512,512] @ x)  [B,512,4096]
    tgemm_k<0><<<dim3(32, 4, NB), blk, SMEM_DB>>>(cv1_w, x, p_y0, 512, 512L * 4096, 512L * 4096);

    // conv3 chain: b -> t -> b1 -> t -> b2  (tensor-core implicit im2col)
    tgemm_k<1><<<dim3(32, 2, NB), blk, SMEM_DB>>>(m0c1, p_y0 + 256L * 4096, p_t,  2304, 512L * 4096, 256L * 4096);
    tgemm_k<1><<<dim3(32, 2, NB), blk, SMEM_DB>>>(m0c2, p_t,                p_b1, 2304, 256L * 4096, 256L * 4096);
    tgemm_k<1><<<dim3(32, 2, NB), blk, SMEM_DB>>>(m1c1, p_b1,               p_t,  2304, 256L * 4096, 256L * 4096);
    tgemm_k<1><<<dim3(32, 2, NB), blk, SMEM_DB>>>(m1c2, p_t,                p_b2, 2304, 256L * 4096, 256L * 4096);

    // value = q @ vproj_w + b  (q[l,c] = b2[c,l] -> TA)   [B,L,256]
    gemm_k<true, false, 1><<<dim3(2, 32, NB), blk>>>(
        p_b2, vproj_w, vproj_b, p_val, 4096, 256, 256, 256L * 4096, 0L, 4096L * 256);

    // off = q @ off_w + b   [B,L,64]
    gemm_k<true, false, 1><<<dim3(1, 32, NB), blk>>>(
        p_b2, off_w, off_b, p_off, 4096, 64, 256, 256L * 4096, 0L, 4096L * 64);

    // aw logits = q @ aw_w + b   [B,L,32]
    gemm_k<true, false, 1><<<dim3(1, 32, NB), blk>>>(
        p_b2, aw_w, aw_b, p_aw, 4096, 32, 256, 256L * 4096, 0L, 4096L * 32);

    // softmax + bilinear sampling -> g_smp [B,L,256]
    sample_k<<<dim3(4096, NB), blk>>>(bbox);

    // attn^T = out_w^T @ samp^T + out_b   ->  g_at [B,D,L]
    gemm_k<true, true, 2><<<dim3(32, 2, NB), blk>>>(
        out_w, p_smp, out_b, p_at, 256, 4096, 256, 0L, 4096L * 256, 256L * 4096);

    // cv2 over virtual concat -> d_out [B,512,4096]
    tgemm_k<2><<<dim3(32, 4, NB), blk, SMEM_DB>>>(cv2_w, nullptr, out, 1280, 0L, 512L * 4096);
}

// round 15
// speedup vs baseline: 2.4417x; 1.0268x over previous
#include <cuda_runtime.h>
#include <cstdint>

// ---------------- problem constants ----------------
// B=8, C1=512, C=256, D=256, NH=8, NP=4, NL=1, H=W=64, L=4096
#define NB 8

// ---------------- scratch buffers (device globals; no allocation) ----------------
__device__ float g_y0 [8L*512*4096];  // cv1 output  [B,512,HW]  (a = ch 0-255, b = ch 256-511)
__device__ float g_t  [8L*256*4096];  // conv temp   [B,256,HW]
__device__ float g_b1 [8L*256*4096];
__device__ float g_b2 [8L*256*4096];
__device__ float g_val[8L*4096*256];  // value       [B,L,D]
__device__ float g_off[8L*4096*64];   // offsets     [B,L,64]
__device__ float g_aw [8L*4096*32];   // attn logits [B,L,32]
__device__ float g_smp[8L*4096*256];  // sampled     [B,L,D]
__device__ float g_at [8L*256*4096];  // attn out    [B,D,L]  (transposed for concat)

// packed weight fragments (bf16 hi/lo, mma.sync m16n8k16 A-fragment layout)
// tile order: cv1[1024] | c0[2304] | c1[2304] | c2[2304] | c3[2304] | cv2[2560] = 12800 tiles
#define WOFF_CV1 0
#define WOFF_C0  1024
#define WOFF_C1  3328
#define WOFF_C2  5632
#define WOFF_C3  7936
#define WOFF_CV2 10240
__device__ uint4 g_wph[12800 * 32];
__device__ uint4 g_wpl[12800 * 32];

static __device__ __forceinline__ float silu_f(float x) {
    return x / (1.0f + __expf(-x));
}

// ---------------- bf16 hi/lo split: pack 8 floats -> 4+4 b32 ----------------
__device__ __forceinline__ void cvt8(float4 a, float4 b, uint4& hp, uint4& lp) {
    float f[8] = { a.x, a.y, a.z, a.w, b.x, b.y, b.z, b.w };
    uint32_t* h = (uint32_t*)&hp;
    uint32_t* l = (uint32_t*)&lp;
#pragma unroll
    for (int i = 0; i < 4; i++) {
        uint32_t u0 = __float_as_uint(f[2 * i]);
        uint32_t u1 = __float_as_uint(f[2 * i + 1]);
        h[i] = __byte_perm(u0, u1, 0x7632);
        float l0 = f[2 * i]     - __uint_as_float(u0 & 0xffff0000u);
        float l1 = f[2 * i + 1] - __uint_as_float(u1 & 0xffff0000u);
        l[i] = __byte_perm(__float_as_uint(l0), __float_as_uint(l1), 0x7632);
    }
}

// ---------------- weight pre-pack: W[M,K] fp32 -> per-tile A fragments ----------------
// tile t = mt*(K/16)+ks; lane frag: r=lane>>2, c=(lane&3)*2 within 16x16 tile
// regs: {(r,c),(r+8,c),(r,c+8),(r+8,c+8)} as bf16x2 pairs -> matches ldmatrix.x4 order
__global__ __launch_bounds__(256)
void packw_k(const float* __restrict__ W, int M, int K, int tile_off)
{
    const int warp = (blockIdx.x * blockDim.x + threadIdx.x) >> 5;
    const int lane = threadIdx.x & 31;
    const int KT = K >> 4;
    if (warp >= (M >> 4) * KT) return;
    const int mt = warp / KT, ks = warp - mt * KT;
    const int r = mt * 16 + (lane >> 2), c = ks * 16 + (lane & 3) * 2;
    const float* p0 = W + (long)r * K + c;
    const float* p1 = W + (long)(r + 8) * K + c;
    float4 fa, fb;
    fa.x = p0[0]; fa.y = p0[1]; fa.z = p1[0]; fa.w = p1[1];
    fb.x = p0[8]; fb.y = p0[9]; fb.z = p1[8]; fb.w = p1[9];
    uint4 hp, lp; cvt8(fa, fb, hp, lp);
    g_wph[(long)(tile_off + warp) * 32 + lane] = hp;
    g_wpl[(long)(tile_off + warp) * 32 + lane] = lp;
}

// ---------------- tensor-core primitives (sm_80-era PTX, valid at compute_103) ----------------
__device__ __forceinline__ uint32_t smem_u32(const void* p) {
    uint32_t a;
    asm("{ .reg .u64 t; cvta.to.shared.u64 t, %1; cvt.u32.u64 %0, t; }" : "=r"(a) : "l"(p));
    return a;
}
__device__ __forceinline__ void ldsm_x4t(uint32_t* r, uint32_t addr) {
    asm volatile("ldmatrix.sync.aligned.m8n8.x4.trans.shared.b16 {%0,%1,%2,%3}, [%4];"
        : "=r"(r[0]), "=r"(r[1]), "=r"(r[2]), "=r"(r[3]) : "r"(addr));
}
__device__ __forceinline__ void mma16816(float* d, const uint32_t* a, const uint32_t* b) {
    asm volatile("mma.sync.aligned.m16n8k16.row.col.f32.bf16.bf16.f32 "
        "{%0,%1,%2,%3}, {%4,%5,%6,%7}, {%8,%9}, {%0,%1,%2,%3};"
        : "+f"(d[0]), "+f"(d[1]), "+f"(d[2]), "+f"(d[3])
        : "r"(a[0]), "r"(a[1]), "r"(a[2]), "r"(a[3]), "r"(b[0]), "r"(b[1]));
}

// ---------------- tensor-core conv-family GEMM ----------------
// C[M,4096] = silu(Wpacked @ Bmat[K,4096]) channel-major, tile 128x128x32, 8 warps @ 64x32
// A fragments: direct coalesced LDG.128 from pre-packed global (no smem/LDSM for A).
// B: double-buffered smem staging, ONE __syncthreads per k-tile.
// MODE 0: cv1   B[k][n] = In[k*4096+n]
// MODE 1: conv3 B[k][n] = implicit im2col (k = ci*9 + ky*3 + kx) from channel-major In
// MODE 2: cv2   B[k][n] = virtual concat [y0(512) | b1(256) | b2(256) | at(256)]
#define BP 136   // B row pad: 128+8 bf16 (272B stride -> conflict-free LDSM)
#define E_BH 0
#define E_BL (32 * BP)
#define STG_E (2 * 32 * BP)                 // uint16 elems per stage = 8704
#define SMEM_DB (2 * STG_E * 2)             // bytes = 34816

template<int MODE>
__global__ __launch_bounds__(256, 1)
void tgemm_k(const uint4* __restrict__ Whi, const uint4* __restrict__ Wlo,
             const float* __restrict__ In, float* __restrict__ Out,
             int K, long sIn, long sOut)
{
    extern __shared__ __align__(16) uint16_t sm[];

    const int tid = threadIdx.x, wid = tid >> 5, lane = tid & 31;
    const int wm = wid & 1, wn = wid >> 1;          // warp grid 2 (m) x 4 (n)
    const int bz = blockIdx.z;
    const int n0 = blockIdx.x * 128;
    const int m0 = blockIdx.y * 128;
    if (MODE != 2) In += (long)bz * sIn;
    Out += (long)bz * sOut;

    const int KT16 = K >> 4;
    const int mtb = (m0 >> 4) + wm * 4;             // this warp's first 16-row tile

    // B-load role: row = tid>>3 (0..31), cg = (tid&7)*16
    const int brow = tid >> 3, bcg = (tid & 7) * 16;
    float rB[16];

    auto loadB = [&](int k0) {
        const int k = k0 + brow;
        if (MODE == 0) {
            const float* src = In + (long)k * 4096 + n0 + bcg;
#pragma unroll
            for (int c = 0; c < 4; c++) *(float4*)(rB + 4 * c) = ((const float4*)src)[c];
        } else if (MODE == 1) {
            const int ci = k / 9, r = k - ci * 9;
            const int ky = r / 3 - 1, kx = (r - (r / 3) * 3) - 1;
            const float* inC = In + (long)ci * 4096;
#pragma unroll
            for (int j = 0; j < 16; j++) {
                const int n = n0 + bcg + j;
                const int y = (n >> 6) + ky, x = (n & 63) + kx;
                rB[j] = (((unsigned)y < 64u) && ((unsigned)x < 64u)) ? inC[(y << 6) + x] : 0.f;
            }
        } else {
            const float* src;
            if (k < 512)       src = g_y0 + (long)bz * (512L * 4096) + (long)k * 4096;
            else if (k < 768)  src = g_b1 + (long)bz * (256L * 4096) + (long)(k - 512) * 4096;
            else if (k < 1024) src = g_b2 + (long)bz * (256L * 4096) + (long)(k - 768) * 4096;
            else               src = g_at + (long)bz * (256L * 4096) + (long)(k - 1024) * 4096;
            src += n0 + bcg;
#pragma unroll
            for (int c = 0; c < 4; c++) *(float4*)(rB + 4 * c) = ((const float4*)src)[c];
        }
    };

    float acc[4][4][4];
#pragma unroll
    for (int i = 0; i < 4; i++)
#pragma unroll
        for (int j = 0; j < 4; j++)
#pragma unroll
            for (int c = 0; c < 4; c++) acc[i][j][c] = 0.f;

    const uint32_t u0 = smem_u32(sm);
    const int nkt = K / 32;
    loadB(0);

    for (int kt = 0; kt < nkt; kt++) {
        const int p = kt & 1;
        uint16_t* SBh = sm + p * STG_E + E_BH;
        uint16_t* SBl = sm + p * STG_E + E_BL;

        // ---- convert + store staged B tile p
        {
            uint4 hp, lp;
            cvt8(*(float4*)rB, *(float4*)(rB + 4), hp, lp);
            *(uint4*)&SBh[brow * BP + bcg] = hp;
            *(uint4*)&SBl[brow * BP + bcg] = lp;
            cvt8(*(float4*)(rB + 8), *(float4*)(rB + 12), hp, lp);
            *(uint4*)&SBh[brow * BP + bcg + 8] = hp;
            *(uint4*)&SBl[brow * BP + bcg + 8] = lp;
        }
        if (kt + 1 < nkt) loadB((kt + 1) * 32);     // prefetch
        __syncthreads();   // ONE barrier per tile: STS(p) visible; prior reads of p^1 done

        const uint32_t uBh = u0 + (uint32_t)(p * STG_E + E_BH) * 2;
        const uint32_t uBl = u0 + (uint32_t)(p * STG_E + E_BL) * 2;

#pragma unroll
        for (int ks = 0; ks < 2; ks++) {
            const int ksg = kt * 2 + ks;
            uint32_t Ah[4][4], Al[4][4], Bh[4][2], Bl[4][2];
            // A fragments: coalesced LDG.128 from packed weights (L1/L2-resident)
            const uint4* ph = Whi + ((long)mtb * KT16 + ksg) * 32 + lane;
            const uint4* pl = Wlo + ((long)mtb * KT16 + ksg) * 32 + lane;
#pragma unroll
            for (int mi = 0; mi < 4; mi++) {
                uint4 h = ph[(long)mi * KT16 * 32];
                Ah[mi][0] = h.x; Ah[mi][1] = h.y; Ah[mi][2] = h.z; Ah[mi][3] = h.w;
                uint4 l = pl[(long)mi * KT16 * 32];
                Al[mi][0] = l.x; Al[mi][1] = l.y; Al[mi][2] = l.z; Al[mi][3] = l.w;
            }
            // B via x4.trans: lanes 0-15 -> rows, lanes 16-31 -> +8 cols
            const int kbrow = ks * 16 + (lane & 15);
            const int bcol  = wn * 32 + ((lane >> 4) & 1) * 8;
#pragma unroll
            for (int njp = 0; njp < 2; njp++) {
                const uint32_t off = (uint32_t)(kbrow * BP + bcol + njp * 16) * 2;
                uint32_t r[4];
                ldsm_x4t(r, uBh + off);
                Bh[2 * njp][0] = r[0]; Bh[2 * njp][1] = r[1];
                Bh[2 * njp + 1][0] = r[2]; Bh[2 * njp + 1][1] = r[3];
                ldsm_x4t(r, uBl + off);
                Bl[2 * njp][0] = r[0]; Bl[2 * njp][1] = r[1];
                Bl[2 * njp + 1][0] = r[2]; Bl[2 * njp + 1][1] = r[3];
            }
#pragma unroll
            for (int mi = 0; mi < 4; mi++)
#pragma unroll
                for (int nj = 0; nj < 4; nj++) {
                    mma16816(acc[mi][nj], Ah[mi], Bh[nj]);
                    mma16816(acc[mi][nj], Ah[mi], Bl[nj]);
                    mma16816(acc[mi][nj], Al[mi], Bh[nj]);
                }
        }
    }

    // ---- epilogue: silu, direct channel-major stores (float2 per fragment row)
    const int er = lane >> 2, ec = (lane & 3) * 2;
#pragma unroll
    for (int mi = 0; mi < 4; mi++) {
        const int r = m0 + wm * 64 + mi * 16 + er;
#pragma unroll
        for (int nj = 0; nj < 4; nj++) {
            const int c = n0 + wn * 32 + nj * 8 + ec;
            float2 v0, v1;
            v0.x = silu_f(acc[mi][nj][0]); v0.y = silu_f(acc[mi][nj][1]);
            v1.x = silu_f(acc[mi][nj][2]); v1.y = silu_f(acc[mi][nj][3]);
            *(float2*)(Out + (long)r * 4096 + c)       = v0;
            *(float2*)(Out + (long)(r + 8) * 4096 + c) = v1;
        }
    }
}

// ---------------- fp32x2 GEMM (attention projections) ----------------
typedef unsigned long long u64;
static __device__ __forceinline__ u64 dup2(float x) {
    u64 r; asm("mov.b64 %0, {%1, %1};" : "=l"(r) : "r"(__float_as_uint(x))); return r;
}
static __device__ __forceinline__ void fma2(u64& d, u64 a, u64 b) {
    asm("fma.rn.f32x2 %0, %1, %2, %3;" : "=l"(d) : "l"(a), "l"(b), "l"(d));
}
static __device__ __forceinline__ float2 unpk2(u64 v) {
    float2 r; asm("mov.b64 {%0, %1}, %2;" : "=f"(r.x), "=f"(r.y) : "l"(v)); return r;
}

// TA: a(m,k)=A[k*M+m] else A[m*K+k].  TB: b(k,n)=B[n*K+k] else B[k*N+n].
// BIAS: 1 bias[n], 2 bias[m]
template<bool TA, bool TB, int BIAS>
__global__ __launch_bounds__(256, 2)
void gemm_k(const float* __restrict__ A, const float* __restrict__ Bm,
            const float* __restrict__ bias, float* __restrict__ Cm,
            int M, int N, int K, long sA, long sB, long sC)
{
    const int bz = blockIdx.z;
    A  += (long)bz * sA;
    Bm += (long)bz * sB;
    Cm += (long)bz * sC;
    const int n0 = blockIdx.x * 128;
    const int m0 = blockIdx.y * 128;
    __shared__ float As[8][128];
    __shared__ float Bs[8][128];
    const int tid = threadIdx.x;
    const int tx = tid & 15, ty = tid >> 4;
    u64 acc2[8][4];
#pragma unroll
    for (int i = 0; i < 8; i++)
#pragma unroll
        for (int j = 0; j < 4; j++) acc2[i][j] = 0ull;

    for (int k0 = 0; k0 < K; k0 += 8) {
        if (TA) {
            const int i = (tid & 31) * 4, kk = tid >> 5;
            *(float4*)&As[kk][i] = *(const float4*)(A + (long)(k0 + kk) * M + m0 + i);
        } else {
            const int mi = tid >> 1, kk4 = (tid & 1) * 4;
            float4 v = *(const float4*)(A + (long)(m0 + mi) * K + k0 + kk4);
            As[kk4 + 0][mi] = v.x; As[kk4 + 1][mi] = v.y;
            As[kk4 + 2][mi] = v.z; As[kk4 + 3][mi] = v.w;
        }
        if (TB) {
            const int ni = tid >> 1, kk4 = (tid & 1) * 4;
            float4 v = make_float4(0.f, 0.f, 0.f, 0.f);
            if (n0 + ni < N) v = *(const float4*)(Bm + (long)(n0 + ni) * K + k0 + kk4);
            Bs[kk4 + 0][ni] = v.x; Bs[kk4 + 1][ni] = v.y;
            Bs[kk4 + 2][ni] = v.z; Bs[kk4 + 3][ni] = v.w;
        } else {
            const int j = (tid & 31) * 4, kk = tid >> 5;
            float4 v = make_float4(0.f, 0.f, 0.f, 0.f);
            if (n0 + j < N) v = *(const float4*)(Bm + (long)(k0 + kk) * N + n0 + j);
            *(float4*)&Bs[kk][j] = v;
        }
        __syncthreads();
#pragma unroll
        for (int kk = 0; kk < 8; kk++) {
            float a[8];
            *(float4*)(a)     = *(float4*)&As[kk][ty * 8];
            *(float4*)(a + 4) = *(float4*)&As[kk][ty * 8 + 4];
            ulonglong2 t0 = *(const ulonglong2*)&Bs[kk][tx * 8];
            ulonglong2 t1 = *(const ulonglong2*)&Bs[kk][tx * 8 + 4];
            u64 b2[4] = { t0.x, t0.y, t1.x, t1.y };
            u64 a2[8];
#pragma unroll
            for (int i = 0; i < 8; i++) a2[i] = dup2(a[i]);
#pragma unroll
            for (int i = 0; i < 8; i++)
#pragma unroll
                for (int j = 0; j < 4; j++) fma2(acc2[i][j], a2[i], b2[j]);
        }
        __syncthreads();
    }
#pragma unroll
    for (int i = 0; i < 8; i++) {
        const int m = m0 + ty * 8 + i;
        const float bmv = (BIAS == 2) ? bias[m] : 0.f;
        float av[8];
#pragma unroll
        for (int j = 0; j < 4; j++) {
            float2 p = unpk2(acc2[i][j]);
            av[2 * j] = p.x; av[2 * j + 1] = p.y;
        }
#pragma unroll
        for (int jj = 0; jj < 2; jj++) {
            const int n = n0 + tx * 8 + jj * 4;
            if (n < N) {
                float4 v;
                v.x = av[jj * 4 + 0]; v.y = av[jj * 4 + 1];
                v.z = av[jj * 4 + 2]; v.w = av[jj * 4 + 3];
                if (BIAS == 1) {
                    v.x += bias[n]; v.y += bias[n + 1]; v.z += bias[n + 2]; v.w += bias[n + 3];
                } else {
                    v.x += bmv; v.y += bmv; v.z += bmv; v.w += bmv;
                }
                *(float4*)(Cm + (long)m * N + n) = v;
            }
        }
    }
}

// ---------------- deformable sampling ----------------
__global__ __launch_bounds__(256)
void sample_k(const float* __restrict__ bbox)
{
    const int l = blockIdx.x, b = blockIdx.y;
    const int h = threadIdx.x >> 5, lane = threadIdx.x & 31;
    const long bl = (long)b * 4096 + l;
    const float* offp = g_off + bl * 64 + h * 8;
    const float* awp  = g_aw  + bl * 32 + h * 4;
    const float bx = bbox[bl * 2 + 0] * 64.f - 0.5f;
    const float by = bbox[bl * 2 + 1] * 64.f - 0.5f;

    const float a0 = awp[0], a1 = awp[1], a2 = awp[2], a3 = awp[3];
    const float mx = fmaxf(fmaxf(a0, a1), fmaxf(a2, a3));
    const float e0 = __expf(a0 - mx), e1 = __expf(a1 - mx);
    const float e2 = __expf(a2 - mx), e3 = __expf(a3 - mx);
    const float inv = 1.f / (e0 + e1 + e2 + e3);
    float ew[4] = { e0 * inv, e1 * inv, e2 * inv, e3 * inv };

    const float* valb = g_val + (long)b * (4096L * 256) + h * 32 + lane;
    float acc = 0.f;
#pragma unroll
    for (int p = 0; p < 4; p++) {
        const float gx = bx + offp[p * 2 + 0];
        const float gy = by + offp[p * 2 + 1];
        const float fx = floorf(gx), fy = floorf(gy);
        const int x0 = (int)fx, y0 = (int)fy;
        const float wx1 = gx - fx, wy1 = gy - fy;
        const float wx0 = 1.f - wx1, wy0 = 1.f - wy1;
        const bool vx0 = (unsigned)x0 < 64u, vx1 = (unsigned)(x0 + 1) < 64u;
        const bool vy0 = (unsigned)y0 < 64u, vy1 = (unsigned)(y0 + 1) < 64u;
        float v = 0.f;
        if (vy0) {
            const float* row = valb + ((long)y0 << 6) * 256;
            if (vx0) v += wx0 * wy0 * row[(long)x0 * 256];
            if (vx1) v += wx1 * wy0 * row[(long)(x0 + 1) * 256];
        }
        if (vy1) {
            const float* row = valb + ((long)(y0 + 1) << 6) * 256;
            if (vx0) v += wx0 * wy1 * row[(long)x0 * 256];
            if (vx1) v += wx1 * wy1 * row[(long)(x0 + 1) * 256];
        }
        acc += ew[p] * v;
    }
    g_smp[bl * 256 + h * 32 + lane] = acc;
}

// ---------------- launch ----------------
extern "C" void kernel_launch(void* const* d_in, const int* in_sizes, int n_in,
                              void* d_out, int out_size)
{
    const float* x       = (const float*)d_in[0];
    const float* bbox    = (const float*)d_in[1];
    const float* cv1_w   = (const float*)d_in[3];
    const float* m0c1    = (const float*)d_in[4];
    const float* m0c2    = (const float*)d_in[5];
    const float* m1c1    = (const float*)d_in[6];
    const float* m1c2    = (const float*)d_in[7];
    const float* vproj_w = (const float*)d_in[8];
    const float* vproj_b = (const float*)d_in[9];
    const float* off_w   = (const float*)d_in[10];
    const float* off_b   = (const float*)d_in[11];
    const float* aw_w    = (const float*)d_in[12];
    const float* aw_b    = (const float*)d_in[13];
    const float* out_w   = (const float*)d_in[14];
    const float* out_b   = (const float*)d_in[15];
    const float* cv2_w   = (const float*)d_in[16];
    float* out = (float*)d_out;

    float *p_y0, *p_t, *p_b1, *p_b2, *p_val, *p_off, *p_aw, *p_smp, *p_at;
    uint4 *p_wph, *p_wpl;
    cudaGetSymbolAddress((void**)&p_y0,  g_y0);
    cudaGetSymbolAddress((void**)&p_t,   g_t);
    cudaGetSymbolAddress((void**)&p_b1,  g_b1);
    cudaGetSymbolAddress((void**)&p_b2,  g_b2);
    cudaGetSymbolAddress((void**)&p_val, g_val);
    cudaGetSymbolAddress((void**)&p_off, g_off);
    cudaGetSymbolAddress((void**)&p_aw,  g_aw);
    cudaGetSymbolAddress((void**)&p_smp, g_smp);
    cudaGetSymbolAddress((void**)&p_at,  g_at);
    cudaGetSymbolAddress((void**)&p_wph, g_wph);
    cudaGetSymbolAddress((void**)&p_wpl, g_wpl);

    cudaFuncSetAttribute(tgemm_k<0>, cudaFuncAttributeMaxDynamicSharedMemorySize, SMEM_DB);
    cudaFuncSetAttribute(tgemm_k<1>, cudaFuncAttributeMaxDynamicSharedMemorySize, SMEM_DB);
    cudaFuncSetAttribute(tgemm_k<2>, cudaFuncAttributeMaxDynamicSharedMemorySize, SMEM_DB);

    dim3 blk(256);

    // pre-pack all conv-family weights into fragment layout (runs every call; ~13MB, negligible)
    packw_k<<<128, blk>>>(cv1_w, 512, 512,  WOFF_CV1);
    packw_k<<<288, blk>>>(m0c1,  256, 2304, WOFF_C0);
    packw_k<<<288, blk>>>(m0c2,  256, 2304, WOFF_C1);
    packw_k<<<288, blk>>>(m1c1,  256, 2304, WOFF_C2);
    packw_k<<<288, blk>>>(m1c2,  256, 2304, WOFF_C3);
    packw_k<<<320, blk>>>(cv2_w, 512, 1280, WOFF_CV2);

    // cv1: y0 = silu(W[512,512] @ x)  [B,512,4096]
    tgemm_k<0><<<dim3(32, 4, NB), blk, SMEM_DB>>>(
        p_wph + (long)WOFF_CV1 * 32, p_wpl + (long)WOFF_CV1 * 32,
        x, p_y0, 512, 512L * 4096, 512L * 4096);

    // conv3 chain: b -> t -> b1 -> t -> b2  (tensor-core implicit im2col)
    tgemm_k<1><<<dim3(32, 2, NB), blk, SMEM_DB>>>(
        p_wph + (long)WOFF_C0 * 32, p_wpl + (long)WOFF_C0 * 32,
        p_y0 + 256L * 4096, p_t,  2304, 512L * 4096, 256L * 4096);
    tgemm_k<1><<<dim3(32, 2, NB), blk, SMEM_DB>>>(
        p_wph + (long)WOFF_C1 * 32, p_wpl + (long)WOFF_C1 * 32,
        p_t, p_b1, 2304, 256L * 4096, 256L * 4096);
    tgemm_k<1><<<dim3(32, 2, NB), blk, SMEM_DB>>>(
        p_wph + (long)WOFF_C2 * 32, p_wpl + (long)WOFF_C2 * 32,
        p_b1, p_t, 2304, 256L * 4096, 256L * 4096);
    tgemm_k<1><<<dim3(32, 2, NB), blk, SMEM_DB>>>(
        p_wph + (long)WOFF_C3 * 32, p_wpl + (long)WOFF_C3 * 32,
        p_t, p_b2, 2304, 256L * 4096, 256L * 4096);

    // value = q @ vproj_w + b  (q[l,c] = b2[c,l] -> TA)   [B,L,256]
    gemm_k<true, false, 1><<<dim3(2, 32, NB), blk>>>(
        p_b2, vproj_w, vproj_b, p_val, 4096, 256, 256, 256L * 4096, 0L, 4096L * 256);

    // off = q @ off_w + b   [B,L,64]
    gemm_k<true, false, 1><<<dim3(1, 32, NB), blk>>>(
        p_b2, off_w, off_b, p_off, 4096, 64, 256, 256L * 4096, 0L, 4096L * 64);

    // aw logits = q @ aw_w + b   [B,L,32]
    gemm_k<true, false, 1><<<dim3(1, 32, NB), blk>>>(
        p_b2, aw_w, aw_b, p_aw, 4096, 32, 256, 256L * 4096, 0L, 4096L * 32);

    // softmax + bilinear sampling -> g_smp [B,L,256]
    sample_k<<<dim3(4096, NB), blk>>>(bbox);

    // attn^T = out_w^T @ samp^T + out_b   ->  g_at [B,D,L]
    gemm_k<true, true, 2><<<dim3(32, 2, NB), blk>>>(
        out_w, p_smp, out_b, p_at, 256, 4096, 256, 0L, 4096L * 256, 256L * 4096);

    // cv2 over virtual concat -> d_out [B,512,4096]
    tgemm_k<2><<<dim3(32, 4, NB), blk, SMEM_DB>>>(
        p_wph + (long)WOFF_CV2 * 32, p_wpl + (long)WOFF_CV2 * 32,
        nullptr, out, 1280, 0L, 512L * 4096);
}